// round 4
// baseline (speedup 1.0000x reference)
#include <cuda_runtime.h>
#include <cuda_bf16.h>
#include <math.h>
#include <stdint.h>

#define Bc   32
#define DIM  256
#define Hc   56
#define Wc   56
#define HWc  (Hc*Wc)          // 3136
#define TOK  (Bc*HWc)         // 100352
#define HID  1024

typedef __nv_bfloat16 bf16;

// ---------------- scratch (device globals; no runtime allocation) ------------
__device__ float g_conv[(size_t)Bc*DIM*HWc];                 // conv out, NCHW
__device__ __align__(256) bf16 g_a_hi[(size_t)TOK*DIM];      // LN out hi
__device__ __align__(256) bf16 g_a_lo[(size_t)TOK*DIM];      // LN out lo
__device__ __align__(256) bf16 g_h_hi[(size_t)TOK*HID];      // hidden hi
__device__ __align__(256) bf16 g_h_lo[(size_t)TOK*HID];      // hidden lo
__device__ __align__(256) bf16 g_w1t_hi[(size_t)HID*DIM];    // w1^T [N=1024][K=256]
__device__ __align__(256) bf16 g_w1t_lo[(size_t)HID*DIM];
__device__ __align__(256) bf16 g_w2t_hi[(size_t)DIM*HID];    // w2^T [N=256][K=1024]
__device__ __align__(256) bf16 g_w2t_lo[(size_t)DIM*HID];

// ---------------- asm primitives (base sm_103, no 'a' features) --------------
__device__ __forceinline__ uint32_t smem_u32(const void* p) {
    uint32_t a;
    asm("{ .reg .u64 t; cvta.to.shared.u64 t, %1; cvt.u32.u64 %0, t; }"
        : "=r"(a) : "l"(p));
    return a;
}
#define CP16(dst, src) \
    asm volatile("cp.async.cg.shared.global [%0], [%1], 16;" \
                 :: "r"(dst), "l"(src) : "memory")
#define CP_COMMIT() asm volatile("cp.async.commit_group;" ::: "memory")
#define CP_WAIT(n)  asm volatile("cp.async.wait_group %0;" :: "n"(n) : "memory")
#define LDSM4(r, addr) \
    asm volatile("ldmatrix.sync.aligned.m8n8.x4.shared.b16 {%0,%1,%2,%3}, [%4];" \
                 : "=r"((r)[0]), "=r"((r)[1]), "=r"((r)[2]), "=r"((r)[3]) \
                 : "r"(addr))
#define MMA16816(d, a, b0v, b1v) \
    asm volatile("mma.sync.aligned.m16n8k16.row.col.f32.bf16.bf16.f32 " \
                 "{%0,%1,%2,%3}, {%4,%5,%6,%7}, {%8,%9}, {%0,%1,%2,%3};" \
                 : "+f"((d)[0]), "+f"((d)[1]), "+f"((d)[2]), "+f"((d)[3]) \
                 : "r"((a)[0]), "r"((a)[1]), "r"((a)[2]), "r"((a)[3]), \
                   "r"(b0v), "r"(b1v))

__device__ __forceinline__ uint32_t sw128(uint32_t off) {
    return off ^ ((off >> 3) & 0x70);
}

// ---------------- 1) depthwise 7x7 conv + bias, NCHW -> NCHW -----------------
#define CROWS 8
__global__ __launch_bounds__(256) void dwconv_kernel(
    const float* __restrict__ x, const float* __restrict__ cw,
    const float* __restrict__ cb)
{
    int bc  = blockIdx.x;
    int c   = bc & (DIM-1);
    int row0 = blockIdx.y * CROWS;

    __shared__ float sx[CROWS+6][64];
    __shared__ float sw[49];

    const float* xp = x + (size_t)bc*HWc;
    int t = threadIdx.x;
    if (t < 49) sw[t] = cw[c*49 + t];

    for (int i = t; i < (CROWS+6)*64; i += 256) {
        int r = i >> 6, col = i & 63;
        int gr = row0 - 3 + r, gc = col - 3;
        float v = 0.f;
        if (gr >= 0 && gr < Hc && gc >= 0 && gc < Wc && col < 62)
            v = xp[gr*Wc + gc];
        sx[r][col] = v;
    }
    __syncthreads();

    float bias = cb[c];
    for (int i = t; i < CROWS*Wc; i += 256) {
        int r = i / Wc, col = i % Wc;
        float acc = bias;
        #pragma unroll
        for (int ki = 0; ki < 7; ki++)
            #pragma unroll
            for (int kj = 0; kj < 7; kj++)
                acc = fmaf(sx[r+ki][col+kj], sw[ki*7+kj], acc);
        g_conv[(size_t)bc*HWc + (size_t)(row0+r)*Wc + col] = acc;
    }
}

// ------- 2) LayerNorm over channels + NCHW->NHWC, emit bf16 hi/lo ------------
__global__ __launch_bounds__(256) void ln_kernel(
    const float* __restrict__ gamma, const float* __restrict__ beta)
{
    int tile = blockIdx.x;
    int b    = tile / (HWc/32);
    int pixbase = (tile % (HWc/32)) * 32;

    __shared__ float s[DIM][33];
    __shared__ float psum[8][32], psq[8][32];
    __shared__ float mu_s[32], rs_s[32];

    int t = threadIdx.x;
    int p = t & 31, gi = t >> 5;

    const float* base = g_conv + (size_t)b*DIM*HWc + pixbase;
    #pragma unroll
    for (int cc = 0; cc < 32; cc++) {
        int c = gi*32 + cc;
        s[c][p] = base[(size_t)c*HWc + p];
    }
    __syncthreads();

    float sum = 0.f, sq = 0.f;
    #pragma unroll
    for (int cc = 0; cc < 32; cc++) {
        float v = s[gi*32+cc][p];
        sum += v; sq = fmaf(v, v, sq);
    }
    psum[gi][p] = sum; psq[gi][p] = sq;
    __syncthreads();

    if (gi == 0) {
        float S = 0.f, Q = 0.f;
        #pragma unroll
        for (int k = 0; k < 8; k++) { S += psum[k][p]; Q += psq[k][p]; }
        float mu  = S * (1.f/DIM);
        float var = Q * (1.f/DIM) - mu*mu;
        mu_s[p] = mu;
        rs_s[p] = rsqrtf(var + 1e-6f);
    }
    __syncthreads();

    size_t tokbase = (size_t)b*HWc + pixbase;
    for (int i = t; i < 32*DIM; i += 256) {
        int pp = i >> 8, c = i & (DIM-1);
        float v = (s[c][pp] - mu_s[pp]) * rs_s[pp] * gamma[c] + beta[c];
        bf16 hv = __float2bfloat16(v);
        size_t o = (tokbase + pp)*DIM + c;
        g_a_hi[o] = hv;
        g_a_lo[o] = __float2bfloat16(v - __bfloat162float(hv));
    }
}

// ------- 2b) transpose + split weights: w1[K,N]->w1t[N,K], w2 likewise -------
__global__ __launch_bounds__(256) void prep_w_kernel(
    const float* __restrict__ w1, const float* __restrict__ w2)
{
    int idx = blockIdx.x * 256 + threadIdx.x;
    if (idx < HID*DIM) {                       // w1t [n=1024][k=256]
        int n = idx >> 8, k = idx & 255;
        float v = w1[(size_t)k*HID + n];
        bf16 h = __float2bfloat16(v);
        g_w1t_hi[idx] = h;
        g_w1t_lo[idx] = __float2bfloat16(v - __bfloat162float(h));
    } else {                                   // w2t [n=256][k=1024]
        int j = idx - HID*DIM;
        int n = j >> 10, k = j & 1023;
        float v = w2[(size_t)k*DIM + n];
        bf16 h = __float2bfloat16(v);
        g_w2t_hi[j] = h;
        g_w2t_lo[j] = __float2bfloat16(v - __bfloat162float(h));
    }
}

// ---------------- 3/4) HMMA split-bf16 GEMM (mma.sync.m16n8k16) --------------
// CTA tile 128x128, BK=64, 2-stage cp.async pipeline.
// Stage layout: Ahi 16K | Alo 16K | Bhi 16K | Blo 16K  (64KB/stage, 2 stages)
// Warps: 2(M) x 4(N); warp tile 64x32; mma tiles 4(M) x 4(N).
// D = Ahi*Bhi^T + Alo*Bhi^T + Ahi*Blo^T  (fp32 accum), PASS-MAJOR issue order
// so consecutive MMAs never share an accumulator (dependency chains broken).
// MODE 1: out = split-bf16(GELU(acc+bias)) -> Ohi/Olo [tok][HID]
// MODE 2: out = acc+bias -> fp32 NCHW (smem-transposed, coalesced)
#define STAGE_BYTES 65536
#define SMEM_TOTAL  (2*STAGE_BYTES)

template<int KTOT, int MODE>
__global__ __launch_bounds__(256, 1) void hgemm_kernel(
    const bf16* __restrict__ Ahi, const bf16* __restrict__ Alo,
    const bf16* __restrict__ Bhi, const bf16* __restrict__ Blo,
    const float* __restrict__ bias,
    bf16* __restrict__ Ohi, bf16* __restrict__ Olo, float* __restrict__ Of)
{
    extern __shared__ char smem[];
    __shared__ float sbias[128];

    const int tid  = threadIdx.x;
    const int wid  = tid >> 5, lane = tid & 31;
    const int warpM = wid >> 2, warpN = wid & 3;        // 2 x 4
    const int n0 = blockIdx.x * 128;
    const size_t m0 = (size_t)blockIdx.y * 128;

    if (tid < 128) sbias[tid] = bias[n0 + tid];

    const uint32_t sb = smem_u32(smem);

    // producer mapping: 1024 16B-chunks per 16KB matrix, 4 iters of 256 thr
    const int pr  = tid >> 3;          // row 0..31 step (base), +32 per iter
    const int seg = tid & 7;           // 16B segment within 128B row

    auto load_stage = [&](int c, int s) {
        const uint32_t st = sb + s * STAGE_BYTES;
        const int k0 = c * 64;
        #pragma unroll
        for (int it = 0; it < 4; it++) {
            const int r = pr + it * 32;
            const uint32_t off = sw128((uint32_t)(r*128 + seg*16));
            const size_t ga = (m0 + r) * (size_t)KTOT + k0 + seg*8;
            const size_t gb = (size_t)(n0 + r) * KTOT + k0 + seg*8;
            CP16(st + off,           Ahi + ga);
            CP16(st + 16384 + off,   Alo + ga);
            CP16(st + 32768 + off,   Bhi + gb);
            CP16(st + 49152 + off,   Blo + gb);
        }
    };

    // ldmatrix per-lane geometry
    const int j  = lane >> 3, lr = lane & 7;
    const int arow  = warpM*64 + ((j & 1) << 3) + lr;   // + mt*16
    const int akoff = (j >> 1) << 3;
    const int brow  = warpN*32 + ((j >> 1) << 3) + lr;  // + p*16
    const int bkoff = (j & 1) << 3;

    float acc[4][4][4] = {};

    load_stage(0, 0); CP_COMMIT();

    const int NC = KTOT / 64;
    #pragma unroll 1
    for (int c = 0; c < NC; c++) {
        if (c + 1 < NC) { load_stage(c + 1, (c + 1) & 1); CP_COMMIT(); CP_WAIT(1); }
        else            { CP_WAIT(0); }
        __syncthreads();

        const uint32_t st = sb + (c & 1) * STAGE_BYTES;
        #pragma unroll
        for (int ks = 0; ks < 4; ks++) {
            const int k16 = ks * 16;
            // load B fragments first (needed by every pass)
            uint32_t bh[4][2], bl[4][2];
            #pragma unroll
            for (int p = 0; p < 2; p++) {
                uint32_t off = sw128((uint32_t)((brow + p*16)*128 + (k16 + bkoff)*2));
                uint32_t r[4];
                LDSM4(r, st + 32768 + off);
                bh[p*2][0]=r[0]; bh[p*2][1]=r[1]; bh[p*2+1][0]=r[2]; bh[p*2+1][1]=r[3];
                LDSM4(r, st + 49152 + off);
                bl[p*2][0]=r[0]; bl[p*2][1]=r[1]; bl[p*2+1][0]=r[2]; bl[p*2+1][1]=r[3];
            }
            uint32_t ah[4][4], al[4][4];
            #pragma unroll
            for (int mt = 0; mt < 4; mt++) {
                uint32_t off = sw128((uint32_t)((arow + mt*16)*128 + (k16 + akoff)*2));
                LDSM4(ah[mt], st + off);
                LDSM4(al[mt], st + 16384 + off);
            }
            // PASS-MAJOR: 16 independent MMAs per pass; acc reuse distance = 16
            #pragma unroll
            for (int mt = 0; mt < 4; mt++)
                #pragma unroll
                for (int nt = 0; nt < 4; nt++)
                    MMA16816(acc[mt][nt], ah[mt], bh[nt][0], bh[nt][1]);
            #pragma unroll
            for (int mt = 0; mt < 4; mt++)
                #pragma unroll
                for (int nt = 0; nt < 4; nt++)
                    MMA16816(acc[mt][nt], al[mt], bh[nt][0], bh[nt][1]);
            #pragma unroll
            for (int mt = 0; mt < 4; mt++)
                #pragma unroll
                for (int nt = 0; nt < 4; nt++)
                    MMA16816(acc[mt][nt], ah[mt], bl[nt][0], bl[nt][1]);
        }
        __syncthreads();
    }

    // ------------------------- epilogue -------------------------------------
    const int mlane = lane >> 2;         // row within 8-row group
    const int nlane = (lane & 3) * 2;    // even col pair

    if (MODE == 1) {
        #pragma unroll
        for (int mt = 0; mt < 4; mt++) {
            const size_t mA = m0 + warpM*64 + mt*16 + mlane;
            #pragma unroll
            for (int nt = 0; nt < 4; nt++) {
                const int nc = warpN*32 + nt*8 + nlane;
                const float b0 = sbias[nc], b1 = sbias[nc + 1];
                #pragma unroll
                for (int half = 0; half < 2; half++) {
                    float v0 = acc[mt][nt][half*2]     + b0;
                    float v1 = acc[mt][nt][half*2 + 1] + b1;
                    v0 = 0.5f * v0 * (1.f + erff(v0 * 0.70710678118654752f));
                    v1 = 0.5f * v1 * (1.f + erff(v1 * 0.70710678118654752f));
                    bf16 h0 = __float2bfloat16(v0), h1 = __float2bfloat16(v1);
                    bf16 l0 = __float2bfloat16(v0 - __bfloat162float(h0));
                    bf16 l1 = __float2bfloat16(v1 - __bfloat162float(h1));
                    uint32_t hp = (uint32_t)*(uint16_t*)&h0 | ((uint32_t)*(uint16_t*)&h1 << 16);
                    uint32_t lp = (uint32_t)*(uint16_t*)&l0 | ((uint32_t)*(uint16_t*)&l1 << 16);
                    size_t o = (mA + half*8) * (size_t)HID + n0 + nc;
                    *(uint32_t*)(Ohi + o) = hp;
                    *(uint32_t*)(Olo + o) = lp;
                }
            }
        }
    } else {
        float* sf = (float*)smem;        // [128 n][132 m] fp32 transpose tile
        #pragma unroll
        for (int mt = 0; mt < 4; mt++) {
            const int mA = warpM*64 + mt*16 + mlane;
            #pragma unroll
            for (int nt = 0; nt < 4; nt++) {
                const int nc = warpN*32 + nt*8 + nlane;
                sf[(nc    )*132 + mA    ] = acc[mt][nt][0];
                sf[(nc + 1)*132 + mA    ] = acc[mt][nt][1];
                sf[(nc    )*132 + mA + 8] = acc[mt][nt][2];
                sf[(nc + 1)*132 + mA + 8] = acc[mt][nt][3];
            }
        }
        __syncthreads();
        #pragma unroll 4
        for (int i = tid; i < 128*128; i += 256) {
            const int n = i >> 7, mm = i & 127;
            const int tok = (int)m0 + mm;
            const int b = tok / HWc, pix = tok % HWc;
            Of[((size_t)b*DIM + n0 + n)*HWc + pix] = sf[n*132 + mm] + sbias[n];
        }
    }
}

// ---------------- launch -----------------------------------------------------
extern "C" void kernel_launch(void* const* d_in, const int* in_sizes, int n_in,
                              void* d_out, int out_size)
{
    const float* x      = (const float*)d_in[0];
    const float* conv_w = (const float*)d_in[1];
    const float* conv_b = (const float*)d_in[2];
    const float* ln_g   = (const float*)d_in[3];
    const float* ln_b   = (const float*)d_in[4];
    const float* w1     = (const float*)d_in[5];
    const float* b1     = (const float*)d_in[6];
    const float* w2     = (const float*)d_in[7];
    const float* b2     = (const float*)d_in[8];
    float* out = (float*)d_out;

    bf16 *p_ahi, *p_alo, *p_hhi, *p_hlo, *p_w1h, *p_w1l, *p_w2h, *p_w2l;
    cudaGetSymbolAddress((void**)&p_ahi, g_a_hi);
    cudaGetSymbolAddress((void**)&p_alo, g_a_lo);
    cudaGetSymbolAddress((void**)&p_hhi, g_h_hi);
    cudaGetSymbolAddress((void**)&p_hlo, g_h_lo);
    cudaGetSymbolAddress((void**)&p_w1h, g_w1t_hi);
    cudaGetSymbolAddress((void**)&p_w1l, g_w1t_lo);
    cudaGetSymbolAddress((void**)&p_w2h, g_w2t_hi);
    cudaGetSymbolAddress((void**)&p_w2l, g_w2t_lo);

    cudaFuncSetAttribute(hgemm_kernel<DIM, 1>,
                         cudaFuncAttributeMaxDynamicSharedMemorySize, SMEM_TOTAL);
    cudaFuncSetAttribute(hgemm_kernel<HID, 2>,
                         cudaFuncAttributeMaxDynamicSharedMemorySize, SMEM_TOTAL);

    dwconv_kernel<<<dim3(Bc*DIM, Hc/CROWS), 256>>>(x, conv_w, conv_b);
    ln_kernel<<<TOK/32, 256>>>(ln_g, ln_b);
    prep_w_kernel<<<(2*HID*DIM)/256, 256>>>(w1, w2);

    // GEMM1: [TOK,256] x w1t[1024,256]^T -> GELU -> h (bf16 split)
    hgemm_kernel<DIM, 1><<<dim3(HID/128, TOK/128), 256, SMEM_TOTAL>>>(
        p_ahi, p_alo, p_w1h, p_w1l, b1, p_hhi, p_hlo, nullptr);
    // GEMM2: [TOK,1024] x w2t[256,1024]^T -> +b2 -> fp32 NCHW out
    hgemm_kernel<HID, 2><<<dim3(DIM/128, TOK/128), 256, SMEM_TOTAL>>>(
        p_hhi, p_hlo, p_w2h, p_w2l, b2, nullptr, nullptr, out);
}

// round 5
// speedup vs baseline: 1.1989x; 1.1989x over previous
#include <cuda_runtime.h>
#include <cuda_fp16.h>
#include <math.h>
#include <stdint.h>

#define Bc   32
#define DIM  256
#define Hc   56
#define Wc   56
#define HWc  (Hc*Wc)          // 3136
#define TOK  (Bc*HWc)         // 100352
#define HID  1024

typedef __half f16;

// ---------------- scratch (device globals; no runtime allocation) ------------
__device__ float g_conv[(size_t)Bc*DIM*HWc];                 // conv out, NCHW
__device__ __align__(256) f16 g_a_hi[(size_t)TOK*DIM];       // LN out hi
__device__ __align__(256) f16 g_a_lo[(size_t)TOK*DIM];       // LN out lo
__device__ __align__(256) f16 g_h_hi[(size_t)TOK*HID];       // hidden hi
__device__ __align__(256) f16 g_h_lo[(size_t)TOK*HID];       // hidden lo
__device__ __align__(256) f16 g_w1t[(size_t)HID*DIM];        // w1^T [N=1024][K=256]
__device__ __align__(256) f16 g_w2t[(size_t)DIM*HID];        // w2^T [N=256][K=1024]

// ---------------- asm primitives (base sm_103, no 'a' features) --------------
__device__ __forceinline__ uint32_t smem_u32(const void* p) {
    uint32_t a;
    asm("{ .reg .u64 t; cvta.to.shared.u64 t, %1; cvt.u32.u64 %0, t; }"
        : "=r"(a) : "l"(p));
    return a;
}
#define CP16(dst, src) \
    asm volatile("cp.async.cg.shared.global [%0], [%1], 16;" \
                 :: "r"(dst), "l"(src) : "memory")
#define CP_COMMIT() asm volatile("cp.async.commit_group;" ::: "memory")
#define CP_WAIT(n)  asm volatile("cp.async.wait_group %0;" :: "n"(n) : "memory")
#define LDSM4(r, addr) \
    asm volatile("ldmatrix.sync.aligned.m8n8.x4.shared.b16 {%0,%1,%2,%3}, [%4];" \
                 : "=r"((r)[0]), "=r"((r)[1]), "=r"((r)[2]), "=r"((r)[3]) \
                 : "r"(addr))
#define MMA16816(d, a, b0v, b1v) \
    asm volatile("mma.sync.aligned.m16n8k16.row.col.f32.f16.f16.f32 " \
                 "{%0,%1,%2,%3}, {%4,%5,%6,%7}, {%8,%9}, {%0,%1,%2,%3};" \
                 : "+f"((d)[0]), "+f"((d)[1]), "+f"((d)[2]), "+f"((d)[3]) \
                 : "r"((a)[0]), "r"((a)[1]), "r"((a)[2]), "r"((a)[3]), \
                   "r"(b0v), "r"(b1v))

__device__ __forceinline__ uint32_t sw128(uint32_t off) {
    return off ^ ((off >> 3) & 0x70);
}
__device__ __forceinline__ uint32_t pack2(f16 a, f16 b) {
    return (uint32_t)*(uint16_t*)&a | ((uint32_t)*(uint16_t*)&b << 16);
}

// ---------------- 1) depthwise 7x7 conv + bias, NCHW -> NCHW -----------------
#define CROWS 8
__global__ __launch_bounds__(256) void dwconv_kernel(
    const float* __restrict__ x, const float* __restrict__ cw,
    const float* __restrict__ cb)
{
    int bc  = blockIdx.x;
    int c   = bc & (DIM-1);
    int row0 = blockIdx.y * CROWS;

    __shared__ float sx[CROWS+6][64];
    __shared__ float sw[49];

    const float* xp = x + (size_t)bc*HWc;
    int t = threadIdx.x;
    if (t < 49) sw[t] = cw[c*49 + t];

    for (int i = t; i < (CROWS+6)*64; i += 256) {
        int r = i >> 6, col = i & 63;
        int gr = row0 - 3 + r, gc = col - 3;
        float v = 0.f;
        if (gr >= 0 && gr < Hc && gc >= 0 && gc < Wc && col < 62)
            v = xp[gr*Wc + gc];
        sx[r][col] = v;
    }
    __syncthreads();

    float bias = cb[c];
    for (int i = t; i < CROWS*Wc; i += 256) {
        int r = i / Wc, col = i % Wc;
        float acc = bias;
        #pragma unroll
        for (int ki = 0; ki < 7; ki++)
            #pragma unroll
            for (int kj = 0; kj < 7; kj++)
                acc = fmaf(sx[r+ki][col+kj], sw[ki*7+kj], acc);
        g_conv[(size_t)bc*HWc + (size_t)(row0+r)*Wc + col] = acc;
    }
}

// ------- 2) LayerNorm over channels + NCHW->NHWC, emit fp16 hi/lo ------------
__global__ __launch_bounds__(256) void ln_kernel(
    const float* __restrict__ gamma, const float* __restrict__ beta)
{
    int tile = blockIdx.x;
    int b    = tile / (HWc/32);
    int pixbase = (tile % (HWc/32)) * 32;

    __shared__ float s[DIM][33];
    __shared__ float psum[8][32], psq[8][32];
    __shared__ float mu_s[32], rs_s[32];

    int t = threadIdx.x;
    int p = t & 31, gi = t >> 5;

    const float* base = g_conv + (size_t)b*DIM*HWc + pixbase;
    #pragma unroll
    for (int cc = 0; cc < 32; cc++) {
        int c = gi*32 + cc;
        s[c][p] = base[(size_t)c*HWc + p];
    }
    __syncthreads();

    float sum = 0.f, sq = 0.f;
    #pragma unroll
    for (int cc = 0; cc < 32; cc++) {
        float v = s[gi*32+cc][p];
        sum += v; sq = fmaf(v, v, sq);
    }
    psum[gi][p] = sum; psq[gi][p] = sq;
    __syncthreads();

    if (gi == 0) {
        float S = 0.f, Q = 0.f;
        #pragma unroll
        for (int k = 0; k < 8; k++) { S += psum[k][p]; Q += psq[k][p]; }
        float mu  = S * (1.f/DIM);
        float var = Q * (1.f/DIM) - mu*mu;
        mu_s[p] = mu;
        rs_s[p] = rsqrtf(var + 1e-6f);
    }
    __syncthreads();

    size_t tokbase = (size_t)b*HWc + pixbase;
    for (int i = t; i < 32*DIM; i += 256) {
        int pp = i >> 8, c = i & (DIM-1);
        float v = (s[c][pp] - mu_s[pp]) * rs_s[pp] * gamma[c] + beta[c];
        f16 hv = __float2half_rn(v);
        size_t o = (tokbase + pp)*DIM + c;
        g_a_hi[o] = hv;
        g_a_lo[o] = __float2half_rn(v - __half2float(hv));
    }
}

// ------- 2b) transpose weights to fp16: w1[K,N]->w1t[N,K], w2 likewise -------
__global__ __launch_bounds__(256) void prep_w_kernel(
    const float* __restrict__ w1, const float* __restrict__ w2)
{
    int idx = blockIdx.x * 256 + threadIdx.x;
    if (idx < HID*DIM) {                       // w1t [n=1024][k=256]
        int n = idx >> 8, k = idx & 255;
        g_w1t[idx] = __float2half_rn(w1[(size_t)k*HID + n]);
    } else {                                   // w2t [n=256][k=1024]
        int j = idx - HID*DIM;
        int n = j >> 10, k = j & 1023;
        g_w2t[j] = __float2half_rn(w2[(size_t)k*DIM + n]);
    }
}

// ---------------- 3/4) HMMA split-fp16 GEMM (mma.sync.m16n8k16) --------------
// CTA tile 128x128, BK=64, 3-stage cp.async pipeline, 512 threads.
// Stage layout: Ahi 16K | Alo 16K | B 16K (48KB/stage, 3 stages = 144KB)
// Warps: 4(M) x 4(N); warp tile 32x32; mma tiles 2(M) x 4(N).
// D = Ahi*B^T + Alo*B^T (fp32 accum); B rounded to single fp16.
// MODE 1: out = split-fp16(GELU(acc+bias)) -> Ohi/Olo [tok][HID]
// MODE 2: out = acc+bias -> fp32 NCHW (smem-transposed, coalesced)
#define STAGE_BYTES 49152
#define SMEM_TOTAL  (3*STAGE_BYTES)    // 147456

template<int KTOT, int MODE>
__global__ __launch_bounds__(512, 1) void hgemm_kernel(
    const f16* __restrict__ Ahi, const f16* __restrict__ Alo,
    const f16* __restrict__ Bw,
    const float* __restrict__ bias,
    f16* __restrict__ Ohi, f16* __restrict__ Olo, float* __restrict__ Of)
{
    extern __shared__ char smem[];
    __shared__ float sbias[128];

    const int tid  = threadIdx.x;
    const int wid  = tid >> 5, lane = tid & 31;
    const int warpM = wid >> 2, warpN = wid & 3;        // 4 x 4
    const int n0 = blockIdx.x * 128;
    const size_t m0 = (size_t)blockIdx.y * 128;

    if (tid < 128) sbias[tid] = bias[n0 + tid];

    const uint32_t sb = smem_u32(smem);

    auto load_stage = [&](int c, int s) {
        const uint32_t st = sb + s * STAGE_BYTES;
        const int k0 = c * 64;
        #pragma unroll
        for (int it = 0; it < 2; it++) {
            const int chunk = tid + it * 512;           // 0..1023
            const int r = chunk >> 3, seg = chunk & 7;
            const uint32_t off = sw128((uint32_t)(r*128 + seg*16));
            const size_t ga = (m0 + r) * (size_t)KTOT + k0 + seg*8;
            const size_t gb = (size_t)(n0 + r) * KTOT + k0 + seg*8;
            CP16(st + off,           Ahi + ga);
            CP16(st + 16384 + off,   Alo + ga);
            CP16(st + 32768 + off,   Bw  + gb);
        }
    };

    // ldmatrix per-lane geometry
    const int j  = lane >> 3, lr = lane & 7;
    const int arow  = warpM*32 + ((j & 1) << 3) + lr;   // + mt*16
    const int akoff = (j >> 1) << 3;
    const int brow  = warpN*32 + ((j >> 1) << 3) + lr;  // + p*16
    const int bkoff = (j & 1) << 3;

    float acc[2][4][4] = {};

    load_stage(0, 0); CP_COMMIT();
    load_stage(1, 1); CP_COMMIT();

    const int NC = KTOT / 64;
    #pragma unroll 1
    for (int c = 0; c < NC; c++) {
        if (c + 1 < NC) { CP_WAIT(1); } else { CP_WAIT(0); }
        __syncthreads();
        if (c + 2 < NC) { load_stage(c + 2, (c + 2) % 3); CP_COMMIT(); }

        const uint32_t st = sb + (c % 3) * STAGE_BYTES;
        #pragma unroll
        for (int ks = 0; ks < 4; ks++) {
            const int k16 = ks * 16;
            uint32_t bh[4][2];
            #pragma unroll
            for (int p = 0; p < 2; p++) {
                uint32_t off = sw128((uint32_t)((brow + p*16)*128 + (k16 + bkoff)*2));
                uint32_t r[4];
                LDSM4(r, st + 32768 + off);
                bh[p*2][0]=r[0]; bh[p*2][1]=r[1]; bh[p*2+1][0]=r[2]; bh[p*2+1][1]=r[3];
            }
            uint32_t ah[2][4], al[2][4];
            #pragma unroll
            for (int mt = 0; mt < 2; mt++) {
                uint32_t off = sw128((uint32_t)((arow + mt*16)*128 + (k16 + akoff)*2));
                LDSM4(ah[mt], st + off);
                LDSM4(al[mt], st + 16384 + off);
            }
            #pragma unroll
            for (int mt = 0; mt < 2; mt++)
                #pragma unroll
                for (int nt = 0; nt < 4; nt++)
                    MMA16816(acc[mt][nt], ah[mt], bh[nt][0], bh[nt][1]);
            #pragma unroll
            for (int mt = 0; mt < 2; mt++)
                #pragma unroll
                for (int nt = 0; nt < 4; nt++)
                    MMA16816(acc[mt][nt], al[mt], bh[nt][0], bh[nt][1]);
        }
    }

    // ------------------------- epilogue -------------------------------------
    const int mlane = lane >> 2;         // row within 8-row group
    const int nlane = (lane & 3) * 2;    // even col pair

    if (MODE == 1) {
        #pragma unroll
        for (int mt = 0; mt < 2; mt++) {
            const size_t mA = m0 + warpM*32 + mt*16 + mlane;
            #pragma unroll
            for (int nt = 0; nt < 4; nt++) {
                const int nc = warpN*32 + nt*8 + nlane;
                const float b0 = sbias[nc], b1 = sbias[nc + 1];
                #pragma unroll
                for (int half = 0; half < 2; half++) {
                    float v0 = acc[mt][nt][half*2]     + b0;
                    float v1 = acc[mt][nt][half*2 + 1] + b1;
                    v0 = 0.5f * v0 * (1.f + erff(v0 * 0.70710678118654752f));
                    v1 = 0.5f * v1 * (1.f + erff(v1 * 0.70710678118654752f));
                    f16 h0 = __float2half_rn(v0), h1 = __float2half_rn(v1);
                    f16 l0 = __float2half_rn(v0 - __half2float(h0));
                    f16 l1 = __float2half_rn(v1 - __half2float(h1));
                    size_t o = (mA + half*8) * (size_t)HID + n0 + nc;
                    *(uint32_t*)(Ohi + o) = pack2(h0, h1);
                    *(uint32_t*)(Olo + o) = pack2(l0, l1);
                }
            }
        }
    } else {
        __syncthreads();                 // stage smem -> transpose buffer reuse
        float* sf = (float*)smem;        // [128 n][132 m] fp32 transpose tile
        #pragma unroll
        for (int mt = 0; mt < 2; mt++) {
            const int mA = warpM*32 + mt*16 + mlane;
            #pragma unroll
            for (int nt = 0; nt < 4; nt++) {
                const int nc = warpN*32 + nt*8 + nlane;
                sf[(nc    )*132 + mA    ] = acc[mt][nt][0];
                sf[(nc + 1)*132 + mA    ] = acc[mt][nt][1];
                sf[(nc    )*132 + mA + 8] = acc[mt][nt][2];
                sf[(nc + 1)*132 + mA + 8] = acc[mt][nt][3];
            }
        }
        __syncthreads();
        #pragma unroll 4
        for (int i = tid; i < 128*128; i += 512) {
            const int n = i >> 7, mm = i & 127;
            const int tok = (int)m0 + mm;
            const int b = tok / HWc, pix = tok % HWc;
            Of[((size_t)b*DIM + n0 + n)*HWc + pix] = sf[n*132 + mm] + sbias[n];
        }
    }
}

// ---------------- launch -----------------------------------------------------
extern "C" void kernel_launch(void* const* d_in, const int* in_sizes, int n_in,
                              void* d_out, int out_size)
{
    const float* x      = (const float*)d_in[0];
    const float* conv_w = (const float*)d_in[1];
    const float* conv_b = (const float*)d_in[2];
    const float* ln_g   = (const float*)d_in[3];
    const float* ln_b   = (const float*)d_in[4];
    const float* w1     = (const float*)d_in[5];
    const float* b1     = (const float*)d_in[6];
    const float* w2     = (const float*)d_in[7];
    const float* b2     = (const float*)d_in[8];
    float* out = (float*)d_out;

    f16 *p_ahi, *p_alo, *p_hhi, *p_hlo, *p_w1t, *p_w2t;
    cudaGetSymbolAddress((void**)&p_ahi, g_a_hi);
    cudaGetSymbolAddress((void**)&p_alo, g_a_lo);
    cudaGetSymbolAddress((void**)&p_hhi, g_h_hi);
    cudaGetSymbolAddress((void**)&p_hlo, g_h_lo);
    cudaGetSymbolAddress((void**)&p_w1t, g_w1t);
    cudaGetSymbolAddress((void**)&p_w2t, g_w2t);

    cudaFuncSetAttribute(hgemm_kernel<DIM, 1>,
                         cudaFuncAttributeMaxDynamicSharedMemorySize, SMEM_TOTAL);
    cudaFuncSetAttribute(hgemm_kernel<HID, 2>,
                         cudaFuncAttributeMaxDynamicSharedMemorySize, SMEM_TOTAL);

    dwconv_kernel<<<dim3(Bc*DIM, Hc/CROWS), 256>>>(x, conv_w, conv_b);
    ln_kernel<<<TOK/32, 256>>>(ln_g, ln_b);
    prep_w_kernel<<<(2*HID*DIM)/256, 256>>>(w1, w2);

    // GEMM1: [TOK,256] x w1t[1024,256]^T -> GELU -> h (fp16 split)
    hgemm_kernel<DIM, 1><<<dim3(HID/128, TOK/128), 512, SMEM_TOTAL>>>(
        p_ahi, p_alo, p_w1t, b1, p_hhi, p_hlo, nullptr);
    // GEMM2: [TOK,1024] x w2t[256,1024]^T -> +b2 -> fp32 NCHW out
    hgemm_kernel<HID, 2><<<dim3(DIM/128, TOK/128), 512, SMEM_TOTAL>>>(
        p_hhi, p_hlo, p_w2t, b2, nullptr, nullptr, out);
}

// round 6
// speedup vs baseline: 1.5242x; 1.2714x over previous
#include <cuda_runtime.h>
#include <cuda_fp16.h>
#include <math.h>
#include <stdint.h>

#define Bc   32
#define DIM  256
#define Hc   56
#define Wc   56
#define HWc  (Hc*Wc)          // 3136
#define TOK  (Bc*HWc)         // 100352
#define HID  1024

typedef __half f16;

// ---------------- scratch (device globals; no runtime allocation) ------------
__device__ float g_conv[(size_t)Bc*DIM*HWc];                 // conv out, NCHW
__device__ __align__(256) f16 g_a_hi[(size_t)TOK*DIM];       // LN out hi
__device__ __align__(256) f16 g_a_lo[(size_t)TOK*DIM];       // LN out lo
__device__ __align__(256) f16 g_h  [(size_t)TOK*HID];        // hidden (single fp16)
__device__ __align__(256) f16 g_w1t[(size_t)HID*DIM];        // w1^T [N=1024][K=256]
__device__ __align__(256) f16 g_w2t[(size_t)DIM*HID];        // w2^T [N=256][K=1024]

// ---------------- asm primitives (base sm_103, no 'a' features) --------------
__device__ __forceinline__ uint32_t smem_u32(const void* p) {
    uint32_t a;
    asm("{ .reg .u64 t; cvta.to.shared.u64 t, %1; cvt.u32.u64 %0, t; }"
        : "=r"(a) : "l"(p));
    return a;
}
#define CP16(dst, src) \
    asm volatile("cp.async.cg.shared.global [%0], [%1], 16;" \
                 :: "r"(dst), "l"(src) : "memory")
#define CP_COMMIT() asm volatile("cp.async.commit_group;" ::: "memory")
#define CP_WAIT(n)  asm volatile("cp.async.wait_group %0;" :: "n"(n) : "memory")
#define LDSM4(r, addr) \
    asm volatile("ldmatrix.sync.aligned.m8n8.x4.shared.b16 {%0,%1,%2,%3}, [%4];" \
                 : "=r"((r)[0]), "=r"((r)[1]), "=r"((r)[2]), "=r"((r)[3]) \
                 : "r"(addr))
#define MMA16816(d, a, b0v, b1v) \
    asm volatile("mma.sync.aligned.m16n8k16.row.col.f32.f16.f16.f32 " \
                 "{%0,%1,%2,%3}, {%4,%5,%6,%7}, {%8,%9}, {%0,%1,%2,%3};" \
                 : "+f"((d)[0]), "+f"((d)[1]), "+f"((d)[2]), "+f"((d)[3]) \
                 : "r"((a)[0]), "r"((a)[1]), "r"((a)[2]), "r"((a)[3]), \
                   "r"(b0v), "r"(b1v))

__device__ __forceinline__ uint32_t sw128(uint32_t off) {
    return off ^ ((off >> 3) & 0x70);
}
__device__ __forceinline__ uint32_t pack2(f16 a, f16 b) {
    return (uint32_t)*(uint16_t*)&a | ((uint32_t)*(uint16_t*)&b << 16);
}

// ---------------- 1) depthwise 7x7 conv + bias, NCHW -> NCHW -----------------
#define CROWS 8
__global__ __launch_bounds__(256) void dwconv_kernel(
    const float* __restrict__ x, const float* __restrict__ cw,
    const float* __restrict__ cb)
{
    int bc  = blockIdx.x;
    int c   = bc & (DIM-1);
    int row0 = blockIdx.y * CROWS;

    __shared__ float sx[CROWS+6][64];
    __shared__ float sw[49];

    const float* xp = x + (size_t)bc*HWc;
    int t = threadIdx.x;
    if (t < 49) sw[t] = cw[c*49 + t];

    for (int i = t; i < (CROWS+6)*64; i += 256) {
        int r = i >> 6, col = i & 63;
        int gr = row0 - 3 + r, gc = col - 3;
        float v = 0.f;
        if (gr >= 0 && gr < Hc && gc >= 0 && gc < Wc && col < 62)
            v = xp[gr*Wc + gc];
        sx[r][col] = v;
    }
    __syncthreads();

    float bias = cb[c];
    for (int i = t; i < CROWS*Wc; i += 256) {
        int r = i / Wc, col = i % Wc;
        float acc = bias;
        #pragma unroll
        for (int ki = 0; ki < 7; ki++)
            #pragma unroll
            for (int kj = 0; kj < 7; kj++)
                acc = fmaf(sx[r+ki][col+kj], sw[ki*7+kj], acc);
        g_conv[(size_t)bc*HWc + (size_t)(row0+r)*Wc + col] = acc;
    }
}

// ------- 2) LayerNorm over channels + NCHW->NHWC, emit fp16 hi/lo ------------
__global__ __launch_bounds__(256) void ln_kernel(
    const float* __restrict__ gamma, const float* __restrict__ beta)
{
    int tile = blockIdx.x;
    int b    = tile / (HWc/32);
    int pixbase = (tile % (HWc/32)) * 32;

    __shared__ float s[DIM][33];
    __shared__ float psum[8][32], psq[8][32];
    __shared__ float mu_s[32], rs_s[32];

    int t = threadIdx.x;
    int p = t & 31, gi = t >> 5;

    const float* base = g_conv + (size_t)b*DIM*HWc + pixbase;
    #pragma unroll
    for (int cc = 0; cc < 32; cc++) {
        int c = gi*32 + cc;
        s[c][p] = base[(size_t)c*HWc + p];
    }
    __syncthreads();

    float sum = 0.f, sq = 0.f;
    #pragma unroll
    for (int cc = 0; cc < 32; cc++) {
        float v = s[gi*32+cc][p];
        sum += v; sq = fmaf(v, v, sq);
    }
    psum[gi][p] = sum; psq[gi][p] = sq;
    __syncthreads();

    if (gi == 0) {
        float S = 0.f, Q = 0.f;
        #pragma unroll
        for (int k = 0; k < 8; k++) { S += psum[k][p]; Q += psq[k][p]; }
        float mu  = S * (1.f/DIM);
        float var = Q * (1.f/DIM) - mu*mu;
        mu_s[p] = mu;
        rs_s[p] = rsqrtf(var + 1e-6f);
    }
    __syncthreads();

    size_t tokbase = (size_t)b*HWc + pixbase;
    for (int i = t; i < 32*DIM; i += 256) {
        int pp = i >> 8, c = i & (DIM-1);
        float v = (s[c][pp] - mu_s[pp]) * rs_s[pp] * gamma[c] + beta[c];
        f16 hv = __float2half_rn(v);
        size_t o = (tokbase + pp)*DIM + c;
        g_a_hi[o] = hv;
        g_a_lo[o] = __float2half_rn(v - __half2float(hv));
    }
}

// ------- 2b) transpose weights to fp16: w1[K,N]->w1t[N,K], w2 likewise -------
__global__ __launch_bounds__(256) void prep_w_kernel(
    const float* __restrict__ w1, const float* __restrict__ w2)
{
    int idx = blockIdx.x * 256 + threadIdx.x;
    if (idx < HID*DIM) {                       // w1t [n=1024][k=256]
        int n = idx >> 8, k = idx & 255;
        g_w1t[idx] = __float2half_rn(w1[(size_t)k*HID + n]);
    } else {                                   // w2t [n=256][k=1024]
        int j = idx - HID*DIM;
        int n = j >> 10, k = j & 1023;
        g_w2t[j] = __float2half_rn(w2[(size_t)k*DIM + n]);
    }
}

// ---------------- 3/4) HMMA fp16 GEMM (mma.sync.m16n8k16) --------------------
// CTA 128x128, BK=64, 256 threads, 2 CTAs/SM.
// Warps: 2(M) x 4(N); warp tile 64x32; mma tiles 4(M) x 4(N).
// NPASS=2: D = Ahi*B^T + Alo*B^T (A split fp16).  NPASS=1: D = A*B^T.
// Stage: A NPASS*16K | B 16K.  NSTAGE=2 (2 syncs/chunk) or 3 (1 sync/chunk).
// MODE 1: out = fp16(GELU(acc+bias)) -> Oh [tok][HID]
// MODE 2: out = acc+bias -> fp32 NCHW (smem-transposed, coalesced)

template<int KTOT, int MODE, int NPASS, int NSTAGE>
__global__ __launch_bounds__(256, 2) void hgemm_kernel(
    const f16* __restrict__ Ahi, const f16* __restrict__ Alo,
    const f16* __restrict__ Bw,
    const float* __restrict__ bias,
    f16* __restrict__ Oh, float* __restrict__ Of)
{
    constexpr int STAGE = (NPASS + 1) * 16384;
    extern __shared__ char smem[];
    __shared__ float sbias[128];

    const int tid  = threadIdx.x;
    const int wid  = tid >> 5, lane = tid & 31;
    const int warpM = wid >> 2, warpN = wid & 3;        // 2 x 4
    const int n0 = blockIdx.x * 128;
    const size_t m0 = (size_t)blockIdx.y * 128;

    if (tid < 128) sbias[tid] = bias[n0 + tid];

    const uint32_t sb = smem_u32(smem);

    auto load_stage = [&](int c, int s) {
        const uint32_t st = sb + s * STAGE;
        const int k0 = c * 64;
        #pragma unroll
        for (int it = 0; it < 4; it++) {
            const int chunk = tid + it * 256;           // 0..1023
            const int r = chunk >> 3, seg = chunk & 7;
            const uint32_t off = sw128((uint32_t)(r*128 + seg*16));
            const size_t ga = (m0 + r) * (size_t)KTOT + k0 + seg*8;
            const size_t gb = (size_t)(n0 + r) * KTOT + k0 + seg*8;
            CP16(st + off, Ahi + ga);
            if (NPASS == 2) CP16(st + 16384 + off, Alo + ga);
            CP16(st + NPASS*16384 + off, Bw + gb);
        }
    };

    // ldmatrix per-lane geometry
    const int j  = lane >> 3, lr = lane & 7;
    const int arow  = warpM*64 + ((j & 1) << 3) + lr;   // + mt*16
    const int akoff = (j >> 1) << 3;
    const int brow  = warpN*32 + ((j >> 1) << 3) + lr;  // + p*16
    const int bkoff = (j & 1) << 3;

    float acc[4][4][4] = {};

    const int NC = KTOT / 64;
    load_stage(0, 0); CP_COMMIT();
    if (NSTAGE == 3 && NC > 1) { load_stage(1, 1); CP_COMMIT(); }

    #pragma unroll 1
    for (int c = 0; c < NC; c++) {
        if (NSTAGE == 2) {
            if (c + 1 < NC) { load_stage(c + 1, (c + 1) & 1); CP_COMMIT(); CP_WAIT(1); }
            else            { CP_WAIT(0); }
            __syncthreads();
        } else {
            if (c + 1 < NC) { CP_WAIT(1); } else { CP_WAIT(0); }
            __syncthreads();
            if (c + 2 < NC) { load_stage(c + 2, (c + 2) % 3); CP_COMMIT(); }
        }

        const uint32_t st = sb + (NSTAGE == 2 ? (c & 1) : (c % 3)) * STAGE;
        #pragma unroll
        for (int ks = 0; ks < 4; ks++) {
            const int k16 = ks * 16;
            uint32_t bh[4][2];
            #pragma unroll
            for (int p = 0; p < 2; p++) {
                uint32_t off = sw128((uint32_t)((brow + p*16)*128 + (k16 + bkoff)*2));
                uint32_t r[4];
                LDSM4(r, st + NPASS*16384 + off);
                bh[p*2][0]=r[0]; bh[p*2][1]=r[1]; bh[p*2+1][0]=r[2]; bh[p*2+1][1]=r[3];
            }
            uint32_t ah[4][4];
            #pragma unroll
            for (int mt = 0; mt < 4; mt++) {
                uint32_t off = sw128((uint32_t)((arow + mt*16)*128 + (k16 + akoff)*2));
                LDSM4(ah[mt], st + off);
            }
            #pragma unroll
            for (int mt = 0; mt < 4; mt++)
                #pragma unroll
                for (int nt = 0; nt < 4; nt++)
                    MMA16816(acc[mt][nt], ah[mt], bh[nt][0], bh[nt][1]);
            if (NPASS == 2) {
                uint32_t al[4][4];
                #pragma unroll
                for (int mt = 0; mt < 4; mt++) {
                    uint32_t off = sw128((uint32_t)((arow + mt*16)*128 + (k16 + akoff)*2));
                    LDSM4(al[mt], st + 16384 + off);
                }
                #pragma unroll
                for (int mt = 0; mt < 4; mt++)
                    #pragma unroll
                    for (int nt = 0; nt < 4; nt++)
                        MMA16816(acc[mt][nt], al[mt], bh[nt][0], bh[nt][1]);
            }
        }
        if (NSTAGE == 2) __syncthreads();   // all warps done with this stage
    }

    // ------------------------- epilogue -------------------------------------
    const int mlane = lane >> 2;         // row within 8-row group
    const int nlane = (lane & 3) * 2;    // even col pair

    if (MODE == 1) {
        #pragma unroll
        for (int mt = 0; mt < 4; mt++) {
            const size_t mA = m0 + warpM*64 + mt*16 + mlane;
            #pragma unroll
            for (int nt = 0; nt < 4; nt++) {
                const int nc = warpN*32 + nt*8 + nlane;
                const float b0 = sbias[nc], b1 = sbias[nc + 1];
                #pragma unroll
                for (int half = 0; half < 2; half++) {
                    float v0 = acc[mt][nt][half*2]     + b0;
                    float v1 = acc[mt][nt][half*2 + 1] + b1;
                    v0 = 0.5f * v0 * (1.f + erff(v0 * 0.70710678118654752f));
                    v1 = 0.5f * v1 * (1.f + erff(v1 * 0.70710678118654752f));
                    size_t o = (mA + half*8) * (size_t)HID + n0 + nc;
                    *(uint32_t*)(Oh + o) = pack2(__float2half_rn(v0),
                                                 __float2half_rn(v1));
                }
            }
        }
    } else {
        if (NSTAGE == 3) __syncthreads();  // smem reuse safety
        float* sf = (float*)smem;          // [128 n][132 m] fp32 transpose tile
        #pragma unroll
        for (int mt = 0; mt < 4; mt++) {
            const int mA = warpM*64 + mt*16 + mlane;
            #pragma unroll
            for (int nt = 0; nt < 4; nt++) {
                const int nc = warpN*32 + nt*8 + nlane;
                sf[(nc    )*132 + mA    ] = acc[mt][nt][0];
                sf[(nc + 1)*132 + mA    ] = acc[mt][nt][1];
                sf[(nc    )*132 + mA + 8] = acc[mt][nt][2];
                sf[(nc + 1)*132 + mA + 8] = acc[mt][nt][3];
            }
        }
        __syncthreads();
        #pragma unroll 4
        for (int i = tid; i < 128*128; i += 256) {
            const int n = i >> 7, mm = i & 127;
            const int tok = (int)m0 + mm;
            const int b = tok / HWc, pix = tok % HWc;
            Of[((size_t)b*DIM + n0 + n)*HWc + pix] = sf[n*132 + mm] + sbias[n];
        }
    }
}

// ---------------- launch -----------------------------------------------------
extern "C" void kernel_launch(void* const* d_in, const int* in_sizes, int n_in,
                              void* d_out, int out_size)
{
    const float* x      = (const float*)d_in[0];
    const float* conv_w = (const float*)d_in[1];
    const float* conv_b = (const float*)d_in[2];
    const float* ln_g   = (const float*)d_in[3];
    const float* ln_b   = (const float*)d_in[4];
    const float* w1     = (const float*)d_in[5];
    const float* b1     = (const float*)d_in[6];
    const float* w2     = (const float*)d_in[7];
    const float* b2     = (const float*)d_in[8];
    float* out = (float*)d_out;

    f16 *p_ahi, *p_alo, *p_h, *p_w1t, *p_w2t;
    cudaGetSymbolAddress((void**)&p_ahi, g_a_hi);
    cudaGetSymbolAddress((void**)&p_alo, g_a_lo);
    cudaGetSymbolAddress((void**)&p_h,   g_h);
    cudaGetSymbolAddress((void**)&p_w1t, g_w1t);
    cudaGetSymbolAddress((void**)&p_w2t, g_w2t);

    // GEMM1: K=256, 2-pass (A split), 2 stages x 48KB = 96KB
    // GEMM2: K=1024, 1-pass, 3 stages x 32KB = 96KB
    constexpr int SMEM1 = 2 * 3 * 16384;
    constexpr int SMEM2 = 3 * 2 * 16384;
    cudaFuncSetAttribute((const void*)hgemm_kernel<DIM, 1, 2, 2>,
                         cudaFuncAttributeMaxDynamicSharedMemorySize, SMEM1);
    cudaFuncSetAttribute((const void*)hgemm_kernel<HID, 2, 1, 3>,
                         cudaFuncAttributeMaxDynamicSharedMemorySize, SMEM2);

    dwconv_kernel<<<dim3(Bc*DIM, Hc/CROWS), 256>>>(x, conv_w, conv_b);
    ln_kernel<<<TOK/32, 256>>>(ln_g, ln_b);
    prep_w_kernel<<<(2*HID*DIM)/256, 256>>>(w1, w2);

    // GEMM1: [TOK,256](split) x w1t -> GELU -> h (fp16)
    hgemm_kernel<DIM, 1, 2, 2><<<dim3(HID/128, TOK/128), 256, SMEM1>>>(
        p_ahi, p_alo, p_w1t, b1, p_h, nullptr);
    // GEMM2: [TOK,1024] x w2t -> +b2 -> fp32 NCHW out
    hgemm_kernel<HID, 2, 1, 3><<<dim3(DIM/128, TOK/128), 256, SMEM2>>>(
        p_h, nullptr, p_w2t, b2, nullptr, out);
}

// round 7
// speedup vs baseline: 1.7618x; 1.1559x over previous
#include <cuda_runtime.h>
#include <cuda_fp16.h>
#include <math.h>
#include <stdint.h>

#define Bc   32
#define DIM  256
#define Hc   56
#define Wc   56
#define HWc  (Hc*Wc)          // 3136
#define TOK  (Bc*HWc)         // 100352
#define HID  1024

typedef __half f16;

// ---------------- scratch (device globals; no runtime allocation) ------------
__device__ float g_conv[(size_t)Bc*DIM*HWc];                 // conv out, NCHW
__device__ __align__(256) f16 g_a  [(size_t)TOK*DIM];        // LN out (fp16)
__device__ __align__(256) f16 g_h  [(size_t)TOK*HID];        // hidden (fp16)
__device__ __align__(256) f16 g_w1t[(size_t)HID*DIM];        // w1^T [N=1024][K=256]
__device__ __align__(256) f16 g_w2t[(size_t)DIM*HID];        // w2^T [N=256][K=1024]

// ---------------- asm primitives (base sm_103, no 'a' features) --------------
__device__ __forceinline__ uint32_t smem_u32(const void* p) {
    uint32_t a;
    asm("{ .reg .u64 t; cvta.to.shared.u64 t, %1; cvt.u32.u64 %0, t; }"
        : "=r"(a) : "l"(p));
    return a;
}
#define CP16(dst, src) \
    asm volatile("cp.async.cg.shared.global [%0], [%1], 16;" \
                 :: "r"(dst), "l"(src) : "memory")
#define CP_COMMIT() asm volatile("cp.async.commit_group;" ::: "memory")
#define CP_WAIT(n)  asm volatile("cp.async.wait_group %0;" :: "n"(n) : "memory")
#define LDSM4(r, addr) \
    asm volatile("ldmatrix.sync.aligned.m8n8.x4.shared.b16 {%0,%1,%2,%3}, [%4];" \
                 : "=r"((r)[0]), "=r"((r)[1]), "=r"((r)[2]), "=r"((r)[3]) \
                 : "r"(addr))
#define MMA16816(d, a, b0v, b1v) \
    asm volatile("mma.sync.aligned.m16n8k16.row.col.f32.f16.f16.f32 " \
                 "{%0,%1,%2,%3}, {%4,%5,%6,%7}, {%8,%9}, {%0,%1,%2,%3};" \
                 : "+f"((d)[0]), "+f"((d)[1]), "+f"((d)[2]), "+f"((d)[3]) \
                 : "r"((a)[0]), "r"((a)[1]), "r"((a)[2]), "r"((a)[3]), \
                   "r"(b0v), "r"(b1v))

__device__ __forceinline__ uint32_t sw128(uint32_t off) {
    return off ^ ((off >> 3) & 0x70);
}
__device__ __forceinline__ uint32_t pack2(f16 a, f16 b) {
    return (uint32_t)*(uint16_t*)&a | ((uint32_t)*(uint16_t*)&b << 16);
}

// ---------------- 1) depthwise 7x7 conv + bias, NCHW -> NCHW -----------------
#define CROWS 8
__global__ __launch_bounds__(256) void dwconv_kernel(
    const float* __restrict__ x, const float* __restrict__ cw,
    const float* __restrict__ cb)
{
    int bc  = blockIdx.x;
    int c   = bc & (DIM-1);
    int row0 = blockIdx.y * CROWS;

    __shared__ float sx[CROWS+6][64];
    __shared__ float sw[49];

    const float* xp = x + (size_t)bc*HWc;
    int t = threadIdx.x;
    if (t < 49) sw[t] = cw[c*49 + t];

    for (int i = t; i < (CROWS+6)*64; i += 256) {
        int r = i >> 6, col = i & 63;
        int gr = row0 - 3 + r, gc = col - 3;
        float v = 0.f;
        if (gr >= 0 && gr < Hc && gc >= 0 && gc < Wc && col < 62)
            v = xp[gr*Wc + gc];
        sx[r][col] = v;
    }
    __syncthreads();

    float bias = cb[c];
    for (int i = t; i < CROWS*Wc; i += 256) {
        int r = i / Wc, col = i % Wc;
        float acc = bias;
        #pragma unroll
        for (int ki = 0; ki < 7; ki++)
            #pragma unroll
            for (int kj = 0; kj < 7; kj++)
                acc = fmaf(sx[r+ki][col+kj], sw[ki*7+kj], acc);
        g_conv[(size_t)bc*HWc + (size_t)(row0+r)*Wc + col] = acc;
    }
}

// ------- 2) LayerNorm over channels + NCHW->NHWC, emit fp16 ------------------
__global__ __launch_bounds__(256) void ln_kernel(
    const float* __restrict__ gamma, const float* __restrict__ beta)
{
    int tile = blockIdx.x;
    int b    = tile / (HWc/32);
    int pixbase = (tile % (HWc/32)) * 32;

    __shared__ float s[DIM][33];
    __shared__ float psum[8][32], psq[8][32];
    __shared__ float mu_s[32], rs_s[32];

    int t = threadIdx.x;
    int p = t & 31, gi = t >> 5;

    const float* base = g_conv + (size_t)b*DIM*HWc + pixbase;
    #pragma unroll
    for (int cc = 0; cc < 32; cc++) {
        int c = gi*32 + cc;
        s[c][p] = base[(size_t)c*HWc + p];
    }
    __syncthreads();

    float sum = 0.f, sq = 0.f;
    #pragma unroll
    for (int cc = 0; cc < 32; cc++) {
        float v = s[gi*32+cc][p];
        sum += v; sq = fmaf(v, v, sq);
    }
    psum[gi][p] = sum; psq[gi][p] = sq;
    __syncthreads();

    if (gi == 0) {
        float S = 0.f, Q = 0.f;
        #pragma unroll
        for (int k = 0; k < 8; k++) { S += psum[k][p]; Q += psq[k][p]; }
        float mu  = S * (1.f/DIM);
        float var = Q * (1.f/DIM) - mu*mu;
        mu_s[p] = mu;
        rs_s[p] = rsqrtf(var + 1e-6f);
    }
    __syncthreads();

    size_t tokbase = (size_t)b*HWc + pixbase;
    // 2 channels per thread -> one 32-bit store
    for (int i = t; i < 32*128; i += 256) {
        int pp = i >> 7, c2 = (i & 127) * 2;
        float mu = mu_s[pp], rs = rs_s[pp];
        float v0 = (s[c2  ][pp] - mu) * rs * gamma[c2  ] + beta[c2  ];
        float v1 = (s[c2+1][pp] - mu) * rs * gamma[c2+1] + beta[c2+1];
        *(uint32_t*)(g_a + (tokbase + pp)*DIM + c2) =
            pack2(__float2half_rn(v0), __float2half_rn(v1));
    }
}

// ------- 2b) transpose weights to fp16: w1[K,N]->w1t[N,K], w2 likewise -------
__global__ __launch_bounds__(256) void prep_w_kernel(
    const float* __restrict__ w1, const float* __restrict__ w2)
{
    int idx = blockIdx.x * 256 + threadIdx.x;
    if (idx < HID*DIM) {                       // w1t [n=1024][k=256]
        int n = idx >> 8, k = idx & 255;
        g_w1t[idx] = __float2half_rn(w1[(size_t)k*HID + n]);
    } else {                                   // w2t [n=256][k=1024]
        int j = idx - HID*DIM;
        int n = j >> 10, k = j & 1023;
        g_w2t[j] = __float2half_rn(w2[(size_t)k*DIM + n]);
    }
}

// ---------------- 3/4) HMMA fp16 GEMM (mma.sync.m16n8k16) --------------------
// CTA 128x128, BK=64, 256 threads, 2 CTAs/SM, 3-stage cp.async pipeline.
// Stage: A 16K | B 16K = 32KB; 3 stages = 96KB/CTA.
// Warps: 2(M) x 4(N); warp tile 64x32; 16 MMA + 6 LDSM per ks.
// MODE 1: out = fp16(GELU(acc+bias)) -> Oh [tok][HID]
// MODE 2: out = acc+bias -> fp32 NCHW (smem-transposed, coalesced)
#define STAGE  32768
#define GSMEM  (3*STAGE)     // 98304

template<int KTOT, int MODE>
__global__ __launch_bounds__(256, 2) void hgemm_kernel(
    const f16* __restrict__ A, const f16* __restrict__ Bw,
    const float* __restrict__ bias,
    f16* __restrict__ Oh, float* __restrict__ Of)
{
    extern __shared__ char smem[];
    __shared__ float sbias[128];

    const int tid  = threadIdx.x;
    const int wid  = tid >> 5, lane = tid & 31;
    const int warpM = wid >> 2, warpN = wid & 3;        // 2 x 4
    const int n0 = blockIdx.x * 128;
    const size_t m0 = (size_t)blockIdx.y * 128;

    if (tid < 128) sbias[tid] = bias[n0 + tid];

    const uint32_t sb = smem_u32(smem);

    // producer: A/B tiles are 128 rows x 64 f16 = 16KB = 1024 16B-chunks each
    const f16* Abase = A + m0 * KTOT;
    const f16* Bbase = Bw + (size_t)n0 * KTOT;

    auto load_stage = [&](int c, int s) {
        const uint32_t st = sb + s * STAGE;
        const uint32_t k0 = (uint32_t)c * 64;
        #pragma unroll
        for (int it = 0; it < 4; it++) {
            const int chunk = tid + it * 256;           // 0..1023
            const uint32_t r = chunk >> 3, seg = chunk & 7;
            const uint32_t off = sw128(r*128 + seg*16);
            const uint32_t g = r * (uint32_t)KTOT + k0 + seg*8;
            CP16(st + off,         Abase + g);
            CP16(st + 16384 + off, Bbase + g);
        }
    };

    // ldmatrix per-lane geometry
    const int j  = lane >> 3, lr = lane & 7;
    const int arow  = warpM*64 + ((j & 1) << 3) + lr;   // + mt*16
    const int akoff = (j >> 1) << 3;
    const int brow  = warpN*32 + ((j >> 1) << 3) + lr;  // + p*16
    const int bkoff = (j & 1) << 3;

    float acc[4][4][4] = {};

    const int NC = KTOT / 64;
    load_stage(0, 0); CP_COMMIT();
    if (NC > 1) { load_stage(1, 1); CP_COMMIT(); }

    #pragma unroll 1
    for (int c = 0; c < NC; c++) {
        if (c + 1 < NC) { CP_WAIT(1); } else { CP_WAIT(0); }
        __syncthreads();
        if (c + 2 < NC) { load_stage(c + 2, (c + 2) % 3); CP_COMMIT(); }

        const uint32_t st = sb + (c % 3) * STAGE;
        #pragma unroll
        for (int ks = 0; ks < 4; ks++) {
            const int k16 = ks * 16;
            uint32_t bh[4][2];
            #pragma unroll
            for (int p = 0; p < 2; p++) {
                uint32_t off = sw128((uint32_t)((brow + p*16)*128 + (k16 + bkoff)*2));
                uint32_t r[4];
                LDSM4(r, st + 16384 + off);
                bh[p*2][0]=r[0]; bh[p*2][1]=r[1]; bh[p*2+1][0]=r[2]; bh[p*2+1][1]=r[3];
            }
            uint32_t ah[4][4];
            #pragma unroll
            for (int mt = 0; mt < 4; mt++) {
                uint32_t off = sw128((uint32_t)((arow + mt*16)*128 + (k16 + akoff)*2));
                LDSM4(ah[mt], st + off);
            }
            #pragma unroll
            for (int mt = 0; mt < 4; mt++)
                #pragma unroll
                for (int nt = 0; nt < 4; nt++)
                    MMA16816(acc[mt][nt], ah[mt], bh[nt][0], bh[nt][1]);
        }
    }

    // ------------------------- epilogue -------------------------------------
    const int mlane = lane >> 2;         // row within 8-row group
    const int nlane = (lane & 3) * 2;    // even col pair

    if (MODE == 1) {
        #pragma unroll
        for (int mt = 0; mt < 4; mt++) {
            const size_t mA = m0 + warpM*64 + mt*16 + mlane;
            #pragma unroll
            for (int nt = 0; nt < 4; nt++) {
                const int nc = warpN*32 + nt*8 + nlane;
                const float b0 = sbias[nc], b1 = sbias[nc + 1];
                #pragma unroll
                for (int half = 0; half < 2; half++) {
                    float v0 = acc[mt][nt][half*2]     + b0;
                    float v1 = acc[mt][nt][half*2 + 1] + b1;
                    v0 = 0.5f * v0 * (1.f + erff(v0 * 0.70710678118654752f));
                    v1 = 0.5f * v1 * (1.f + erff(v1 * 0.70710678118654752f));
                    size_t o = (mA + half*8) * (size_t)HID + n0 + nc;
                    *(uint32_t*)(Oh + o) = pack2(__float2half_rn(v0),
                                                 __float2half_rn(v1));
                }
            }
        }
    } else {
        __syncthreads();                   // stage smem free for reuse
        float* sf = (float*)smem;          // [128 n][132 m] fp32 transpose tile
        #pragma unroll
        for (int mt = 0; mt < 4; mt++) {
            const int mA = warpM*64 + mt*16 + mlane;
            #pragma unroll
            for (int nt = 0; nt < 4; nt++) {
                const int nc = warpN*32 + nt*8 + nlane;
                sf[(nc    )*132 + mA    ] = acc[mt][nt][0];
                sf[(nc + 1)*132 + mA    ] = acc[mt][nt][1];
                sf[(nc    )*132 + mA + 8] = acc[mt][nt][2];
                sf[(nc + 1)*132 + mA + 8] = acc[mt][nt][3];
            }
        }
        __syncthreads();
        #pragma unroll 4
        for (int i = tid; i < 128*128; i += 256) {
            const int n = i >> 7, mm = i & 127;
            const int tok = (int)m0 + mm;
            const int b = tok / HWc, pix = tok % HWc;
            Of[((size_t)b*DIM + n0 + n)*HWc + pix] = sf[n*132 + mm] + sbias[n];
        }
    }
}

// ---------------- launch -----------------------------------------------------
extern "C" void kernel_launch(void* const* d_in, const int* in_sizes, int n_in,
                              void* d_out, int out_size)
{
    const float* x      = (const float*)d_in[0];
    const float* conv_w = (const float*)d_in[1];
    const float* conv_b = (const float*)d_in[2];
    const float* ln_g   = (const float*)d_in[3];
    const float* ln_b   = (const float*)d_in[4];
    const float* w1     = (const float*)d_in[5];
    const float* b1     = (const float*)d_in[6];
    const float* w2     = (const float*)d_in[7];
    const float* b2     = (const float*)d_in[8];
    float* out = (float*)d_out;

    f16 *p_a, *p_h, *p_w1t, *p_w2t;
    cudaGetSymbolAddress((void**)&p_a,   g_a);
    cudaGetSymbolAddress((void**)&p_h,   g_h);
    cudaGetSymbolAddress((void**)&p_w1t, g_w1t);
    cudaGetSymbolAddress((void**)&p_w2t, g_w2t);

    cudaFuncSetAttribute((const void*)hgemm_kernel<DIM, 1>,
                         cudaFuncAttributeMaxDynamicSharedMemorySize, GSMEM);
    cudaFuncSetAttribute((const void*)hgemm_kernel<HID, 2>,
                         cudaFuncAttributeMaxDynamicSharedMemorySize, GSMEM);

    dwconv_kernel<<<dim3(Bc*DIM, Hc/CROWS), 256>>>(x, conv_w, conv_b);
    ln_kernel<<<TOK/32, 256>>>(ln_g, ln_b);
    prep_w_kernel<<<(2*HID*DIM)/256, 256>>>(w1, w2);

    // GEMM1: [TOK,256] x w1t -> GELU -> h (fp16)
    hgemm_kernel<DIM, 1><<<dim3(HID/128, TOK/128), 256, GSMEM>>>(
        p_a, p_w1t, b1, p_h, nullptr);
    // GEMM2: [TOK,1024] x w2t -> +b2 -> fp32 NCHW out
    hgemm_kernel<HID, 2><<<dim3(DIM/128, TOK/128), 256, GSMEM>>>(
        p_h, p_w2t, b2, nullptr, out);
}

// round 8
// speedup vs baseline: 2.5135x; 1.4267x over previous
#include <cuda_runtime.h>
#include <cuda_fp16.h>
#include <math.h>
#include <stdint.h>

#define Bc   32
#define DIM  256
#define Hc   56
#define Wc   56
#define HWc  (Hc*Wc)          // 3136
#define TOK  (Bc*HWc)         // 100352
#define HID  1024

typedef __half f16;

// ---------------- scratch (device globals; no runtime allocation) ------------
__device__ float g_conv[(size_t)Bc*DIM*HWc];                 // conv out, NCHW
__device__ __align__(256) f16 g_a  [(size_t)TOK*DIM];        // LN out (fp16)
__device__ __align__(256) f16 g_h  [(size_t)TOK*HID];        // hidden (fp16)
__device__ __align__(256) f16 g_w1t[(size_t)HID*DIM];        // w1^T [N=1024][K=256]
__device__ __align__(256) f16 g_w2t[(size_t)DIM*HID];        // w2^T [N=256][K=1024]

// ---------------- asm primitives (base sm_103, no 'a' features) --------------
__device__ __forceinline__ uint32_t smem_u32(const void* p) {
    uint32_t a;
    asm("{ .reg .u64 t; cvta.to.shared.u64 t, %1; cvt.u32.u64 %0, t; }"
        : "=r"(a) : "l"(p));
    return a;
}
#define CP16(dst, src) \
    asm volatile("cp.async.cg.shared.global [%0], [%1], 16;" \
                 :: "r"(dst), "l"(src) : "memory")
#define CP_COMMIT() asm volatile("cp.async.commit_group;" ::: "memory")
#define CP_WAIT(n)  asm volatile("cp.async.wait_group %0;" :: "n"(n) : "memory")
#define LDSM4(r, addr) \
    asm volatile("ldmatrix.sync.aligned.m8n8.x4.shared.b16 {%0,%1,%2,%3}, [%4];" \
                 : "=r"((r)[0]), "=r"((r)[1]), "=r"((r)[2]), "=r"((r)[3]) \
                 : "r"(addr))
#define MMA16816(d, a, b0v, b1v) \
    asm volatile("mma.sync.aligned.m16n8k16.row.col.f32.f16.f16.f32 " \
                 "{%0,%1,%2,%3}, {%4,%5,%6,%7}, {%8,%9}, {%0,%1,%2,%3};" \
                 : "+f"((d)[0]), "+f"((d)[1]), "+f"((d)[2]), "+f"((d)[3]) \
                 : "r"((a)[0]), "r"((a)[1]), "r"((a)[2]), "r"((a)[3]), \
                   "r"(b0v), "r"(b1v))

__device__ __forceinline__ uint32_t sw128(uint32_t off) {
    return off ^ ((off >> 3) & 0x70);
}
__device__ __forceinline__ uint32_t pack2(f16 a, f16 b) {
    return (uint32_t)*(uint16_t*)&a | ((uint32_t)*(uint16_t*)&b << 16);
}

// ------- 1) depthwise 7x7 conv + bias: one block per (b,c) plane -------------
__global__ __launch_bounds__(256) void dwconv_kernel(
    const float* __restrict__ x, const float* __restrict__ cw,
    const float* __restrict__ cb)
{
    const int bc = blockIdx.x;            // b*DIM + c
    const int c  = bc & (DIM-1);

    __shared__ float sx[62][64];          // rows -3..58, cols -3..60 (pad 64)
    __shared__ float sw[49];

    const float* xp = x + (size_t)bc*HWc;
    const int t = threadIdx.x;
    if (t < 49) sw[t] = cw[c*49 + t];

    for (int i = t; i < 62*64; i += 256) {
        const int r = i >> 6, col = i & 63;
        const int gr = r - 3, gc = col - 3;
        float v = 0.f;
        if (gr >= 0 && gr < Hc && gc >= 0 && gc < Wc)
            v = xp[gr*Wc + gc];
        sx[r][col] = v;
    }
    __syncthreads();

    const float bias = cb[c];
    float* op = g_conv + (size_t)bc*HWc;
    const int col = t & 63, r0 = t >> 6;  // 4 rows x 64 cols per iteration
    if (col < Wc) {
        #pragma unroll
        for (int rr = r0; rr < Hc; rr += 4) {
            float acc = bias;
            #pragma unroll
            for (int ki = 0; ki < 7; ki++)
                #pragma unroll
                for (int kj = 0; kj < 7; kj++)
                    acc = fmaf(sx[rr+ki][col+kj], sw[ki*7+kj], acc);
            op[rr*Wc + col] = acc;
        }
    }
}

// ------- 2) LayerNorm over channels + NCHW->NHWC, emit fp16 ------------------
__global__ __launch_bounds__(256) void ln_kernel(
    const float* __restrict__ gamma, const float* __restrict__ beta)
{
    int tile = blockIdx.x;
    int b    = tile / (HWc/32);
    int pixbase = (tile % (HWc/32)) * 32;

    __shared__ float s[DIM][33];
    __shared__ float psum[8][32], psq[8][32];
    __shared__ float mu_s[32], rs_s[32];

    int t = threadIdx.x;
    int p = t & 31, gi = t >> 5;

    const float* base = g_conv + (size_t)b*DIM*HWc + pixbase;
    #pragma unroll
    for (int cc = 0; cc < 32; cc++) {
        int c = gi*32 + cc;
        s[c][p] = base[(size_t)c*HWc + p];
    }
    __syncthreads();

    float sum = 0.f, sq = 0.f;
    #pragma unroll
    for (int cc = 0; cc < 32; cc++) {
        float v = s[gi*32+cc][p];
        sum += v; sq = fmaf(v, v, sq);
    }
    psum[gi][p] = sum; psq[gi][p] = sq;
    __syncthreads();

    if (gi == 0) {
        float S = 0.f, Q = 0.f;
        #pragma unroll
        for (int k = 0; k < 8; k++) { S += psum[k][p]; Q += psq[k][p]; }
        float mu  = S * (1.f/DIM);
        float var = Q * (1.f/DIM) - mu*mu;
        mu_s[p] = mu;
        rs_s[p] = rsqrtf(var + 1e-6f);
    }
    __syncthreads();

    size_t tokbase = (size_t)b*HWc + pixbase;
    for (int i = t; i < 32*128; i += 256) {
        int pp = i >> 7, c2 = (i & 127) * 2;
        float mu = mu_s[pp], rs = rs_s[pp];
        float v0 = (s[c2  ][pp] - mu) * rs * gamma[c2  ] + beta[c2  ];
        float v1 = (s[c2+1][pp] - mu) * rs * gamma[c2+1] + beta[c2+1];
        *(uint32_t*)(g_a + (tokbase + pp)*DIM + c2) =
            pack2(__float2half_rn(v0), __float2half_rn(v1));
    }
}

// ------- 2b) transpose weights to fp16: w1[K,N]->w1t[N,K], w2 likewise -------
__global__ __launch_bounds__(256) void prep_w_kernel(
    const float* __restrict__ w1, const float* __restrict__ w2)
{
    int idx = blockIdx.x * 256 + threadIdx.x;
    if (idx < HID*DIM) {                       // w1t [n=1024][k=256]
        int n = idx >> 8, k = idx & 255;
        g_w1t[idx] = __float2half_rn(w1[(size_t)k*HID + n]);
    } else {                                   // w2t [n=256][k=1024]
        int j = idx - HID*DIM;
        int n = j >> 10, k = j & 1023;
        g_w2t[j] = __float2half_rn(w2[(size_t)k*DIM + n]);
    }
}

// ---------------- 3/4) HMMA fp16 GEMM (mma.sync.m16n8k16) --------------------
// CTA 128x128, BK=64, 256 threads, 2 CTAs/SM, 3-stage cp.async pipeline.
// Stage: A 16K | B 16K = 32KB; 3 stages = 96KB/CTA.
// All LDSM addresses precomputed; per-k-step address = base ^ (32*ks)
// (SW128 identity: the 32B k-offset occupies exactly the XOR bits [5:6]).
// MODE 1: out = fp16(GELU(acc+bias)) -> Oh [tok][HID]
// MODE 2: out = acc+bias -> fp32 NCHW (smem-transposed, coalesced)
#define STAGE  32768
#define GSMEM  (3*STAGE)     // 98304

template<int KTOT, int MODE>
__global__ __launch_bounds__(256, 2) void hgemm_kernel(
    const f16* __restrict__ A, const f16* __restrict__ Bw,
    const float* __restrict__ bias,
    f16* __restrict__ Oh, float* __restrict__ Of)
{
    extern __shared__ char smem[];
    __shared__ float sbias[128];

    const int tid  = threadIdx.x;
    const int wid  = tid >> 5, lane = tid & 31;
    const int warpM = wid >> 2, warpN = wid & 3;        // 2 x 4
    const int n0 = blockIdx.x * 128;
    const size_t m0 = (size_t)blockIdx.y * 128;

    if (tid < 128) sbias[tid] = bias[n0 + tid];

    const uint32_t sb = smem_u32(smem);

    // ---- producer: precomputed smem offsets + gmem row offsets --------------
    const f16* Abase = A + m0 * KTOT;
    const f16* Bbase = Bw + (size_t)n0 * KTOT;
    uint32_t soff[4], goff[4];
    #pragma unroll
    for (int it = 0; it < 4; it++) {
        const int chunk = tid + it * 256;               // 0..1023
        const uint32_t r = chunk >> 3, seg = chunk & 7;
        soff[it] = sw128(r*128 + seg*16);
        goff[it] = r * (uint32_t)KTOT + seg*8;
    }
    auto load_stage = [&](int c, int s) {
        const uint32_t st = sb + s * STAGE;
        const uint32_t k0 = (uint32_t)c * 64;
        #pragma unroll
        for (int it = 0; it < 4; it++) {
            CP16(st + soff[it],         Abase + goff[it] + k0);
            CP16(st + 16384 + soff[it], Bbase + goff[it] + k0);
        }
    };

    // ---- consumer: precomputed LDSM base offsets -----------------------------
    const int j  = lane >> 3, lr = lane & 7;
    const uint32_t mask = (uint32_t)lr << 4;            // row&7 == lr for all tiles
    uint32_t aoff[4], boff[2];
    #pragma unroll
    for (int mt = 0; mt < 4; mt++) {
        const uint32_t row = warpM*64 + ((j & 1) << 3) + lr + mt*16;
        aoff[mt] = row*128 + (((uint32_t)(j >> 1) << 4) ^ mask);
    }
    #pragma unroll
    for (int p = 0; p < 2; p++) {
        const uint32_t row = warpN*32 + ((j >> 1) << 3) + lr + p*16;
        boff[p] = 16384 + row*128 + (((uint32_t)(j & 1) << 4) ^ mask);
    }

    float acc[4][4][4] = {};

    const int NC = KTOT / 64;
    load_stage(0, 0); CP_COMMIT();
    if (NC > 1) { load_stage(1, 1); CP_COMMIT(); }

    int s_use = 0, s_load = 2;
    #pragma unroll 1
    for (int c = 0; c < NC; c++) {
        if (c + 1 < NC) { CP_WAIT(1); } else { CP_WAIT(0); }
        __syncthreads();
        if (c + 2 < NC) {
            load_stage(c + 2, s_load); CP_COMMIT();
            if (++s_load == 3) s_load = 0;
        }

        const uint32_t st = sb + s_use * STAGE;
        if (++s_use == 3) s_use = 0;
        const uint32_t a0 = st + aoff[0], a1 = st + aoff[1];
        const uint32_t a2 = st + aoff[2], a3 = st + aoff[3];
        const uint32_t b0 = st + boff[0], b1 = st + boff[1];

        #pragma unroll
        for (int ks = 0; ks < 4; ks++) {
            const uint32_t kx = 32u * ks;               // XOR bits [5:6]
            uint32_t bh[4][2];
            {
                uint32_t r[4];
                LDSM4(r, b0 ^ kx);
                bh[0][0]=r[0]; bh[0][1]=r[1]; bh[1][0]=r[2]; bh[1][1]=r[3];
                LDSM4(r, b1 ^ kx);
                bh[2][0]=r[0]; bh[2][1]=r[1]; bh[3][0]=r[2]; bh[3][1]=r[3];
            }
            uint32_t ah[4][4];
            LDSM4(ah[0], a0 ^ kx);
            LDSM4(ah[1], a1 ^ kx);
            LDSM4(ah[2], a2 ^ kx);
            LDSM4(ah[3], a3 ^ kx);

            #pragma unroll
            for (int mt = 0; mt < 4; mt++)
                #pragma unroll
                for (int nt = 0; nt < 4; nt++)
                    MMA16816(acc[mt][nt], ah[mt], bh[nt][0], bh[nt][1]);
        }
    }

    // ------------------------- epilogue -------------------------------------
    const int mlane = lane >> 2;         // row within 8-row group
    const int nlane = (lane & 3) * 2;    // even col pair

    if (MODE == 1) {
        #pragma unroll
        for (int mt = 0; mt < 4; mt++) {
            const size_t mA = m0 + warpM*64 + mt*16 + mlane;
            #pragma unroll
            for (int nt = 0; nt < 4; nt++) {
                const int nc = warpN*32 + nt*8 + nlane;
                const float b0 = sbias[nc], b1 = sbias[nc + 1];
                #pragma unroll
                for (int half = 0; half < 2; half++) {
                    float v0 = acc[mt][nt][half*2]     + b0;
                    float v1 = acc[mt][nt][half*2 + 1] + b1;
                    v0 = 0.5f * v0 * (1.f + erff(v0 * 0.70710678118654752f));
                    v1 = 0.5f * v1 * (1.f + erff(v1 * 0.70710678118654752f));
                    size_t o = (mA + half*8) * (size_t)HID + n0 + nc;
                    *(uint32_t*)(Oh + o) = pack2(__float2half_rn(v0),
                                                 __float2half_rn(v1));
                }
            }
        }
    } else {
        __syncthreads();                   // stage smem free for reuse
        float* sf = (float*)smem;          // [128 n][132 m] fp32 transpose tile
        #pragma unroll
        for (int mt = 0; mt < 4; mt++) {
            const int mA = warpM*64 + mt*16 + mlane;
            #pragma unroll
            for (int nt = 0; nt < 4; nt++) {
                const int nc = warpN*32 + nt*8 + nlane;
                sf[(nc    )*132 + mA    ] = acc[mt][nt][0];
                sf[(nc + 1)*132 + mA    ] = acc[mt][nt][1];
                sf[(nc    )*132 + mA + 8] = acc[mt][nt][2];
                sf[(nc + 1)*132 + mA + 8] = acc[mt][nt][3];
            }
        }
        __syncthreads();
        #pragma unroll 4
        for (int i = tid; i < 128*128; i += 256) {
            const int n = i >> 7, mm = i & 127;
            const int tok = (int)m0 + mm;
            const int b = tok / HWc, pix = tok % HWc;
            Of[((size_t)b*DIM + n0 + n)*HWc + pix] = sf[n*132 + mm] + sbias[n];
        }
    }
}

// ---------------- launch -----------------------------------------------------
extern "C" void kernel_launch(void* const* d_in, const int* in_sizes, int n_in,
                              void* d_out, int out_size)
{
    const float* x      = (const float*)d_in[0];
    const float* conv_w = (const float*)d_in[1];
    const float* conv_b = (const float*)d_in[2];
    const float* ln_g   = (const float*)d_in[3];
    const float* ln_b   = (const float*)d_in[4];
    const float* w1     = (const float*)d_in[5];
    const float* b1     = (const float*)d_in[6];
    const float* w2     = (const float*)d_in[7];
    const float* b2     = (const float*)d_in[8];
    float* out = (float*)d_out;

    f16 *p_a, *p_h, *p_w1t, *p_w2t;
    cudaGetSymbolAddress((void**)&p_a,   g_a);
    cudaGetSymbolAddress((void**)&p_h,   g_h);
    cudaGetSymbolAddress((void**)&p_w1t, g_w1t);
    cudaGetSymbolAddress((void**)&p_w2t, g_w2t);

    cudaFuncSetAttribute((const void*)hgemm_kernel<DIM, 1>,
                         cudaFuncAttributeMaxDynamicSharedMemorySize, GSMEM);
    cudaFuncSetAttribute((const void*)hgemm_kernel<HID, 2>,
                         cudaFuncAttributeMaxDynamicSharedMemorySize, GSMEM);

    dwconv_kernel<<<Bc*DIM, 256>>>(x, conv_w, conv_b);
    ln_kernel<<<TOK/32, 256>>>(ln_g, ln_b);
    prep_w_kernel<<<(2*HID*DIM)/256, 256>>>(w1, w2);

    // GEMM1: [TOK,256] x w1t -> GELU -> h (fp16)
    hgemm_kernel<DIM, 1><<<dim3(HID/128, TOK/128), 256, GSMEM>>>(
        p_a, p_w1t, b1, p_h, nullptr);
    // GEMM2: [TOK,1024] x w2t -> +b2 -> fp32 NCHW out
    hgemm_kernel<HID, 2><<<dim3(DIM/128, TOK/128), 256, GSMEM>>>(
        p_h, p_w2t, b2, nullptr, out);
}

// round 9
// speedup vs baseline: 2.6198x; 1.0423x over previous
#include <cuda_runtime.h>
#include <cuda_fp16.h>
#include <math.h>
#include <stdint.h>

#define Bc   32
#define DIM  256
#define Hc   56
#define Wc   56
#define HWc  (Hc*Wc)          // 3136
#define TOK  (Bc*HWc)         // 100352
#define HID  1024

typedef __half f16;

// ---------------- scratch (device globals; no runtime allocation) ------------
__device__ float g_conv[(size_t)Bc*DIM*HWc];                 // conv out, NCHW
__device__ __align__(256) f16 g_a  [(size_t)TOK*DIM];        // LN out (fp16)
__device__ __align__(256) f16 g_h  [(size_t)TOK*HID];        // hidden (fp16)
__device__ __align__(256) f16 g_w1t[(size_t)HID*DIM];        // w1^T [N=1024][K=256]
__device__ __align__(256) f16 g_w2t[(size_t)DIM*HID];        // w2^T [N=256][K=1024]

// ---------------- asm primitives (base sm_103, no 'a' features) --------------
__device__ __forceinline__ uint32_t smem_u32(const void* p) {
    uint32_t a;
    asm("{ .reg .u64 t; cvta.to.shared.u64 t, %1; cvt.u32.u64 %0, t; }"
        : "=r"(a) : "l"(p));
    return a;
}
#define CP16(dst, src) \
    asm volatile("cp.async.cg.shared.global [%0], [%1], 16;" \
                 :: "r"(dst), "l"(src) : "memory")
#define CP_COMMIT() asm volatile("cp.async.commit_group;" ::: "memory")
#define CP_WAIT(n)  asm volatile("cp.async.wait_group %0;" :: "n"(n) : "memory")
#define LDSM4(r, addr) \
    asm volatile("ldmatrix.sync.aligned.m8n8.x4.shared.b16 {%0,%1,%2,%3}, [%4];" \
                 : "=r"((r)[0]), "=r"((r)[1]), "=r"((r)[2]), "=r"((r)[3]) \
                 : "r"(addr))
#define MMA16816(d, a, b0v, b1v) \
    asm volatile("mma.sync.aligned.m16n8k16.row.col.f32.f16.f16.f32 " \
                 "{%0,%1,%2,%3}, {%4,%5,%6,%7}, {%8,%9}, {%0,%1,%2,%3};" \
                 : "+f"((d)[0]), "+f"((d)[1]), "+f"((d)[2]), "+f"((d)[3]) \
                 : "r"((a)[0]), "r"((a)[1]), "r"((a)[2]), "r"((a)[3]), \
                   "r"(b0v), "r"(b1v))

__device__ __forceinline__ uint32_t sw128(uint32_t off) {
    return off ^ ((off >> 3) & 0x70);
}
__device__ __forceinline__ uint32_t pack2(f16 a, f16 b) {
    return (uint32_t)*(uint16_t*)&a | ((uint32_t)*(uint16_t*)&b << 16);
}

// Fast exact-GELU: Abramowitz-Stegun 7.1.26 erf (|abs err| <= 1.5e-7),
// branch-free, 2 MUFU. gelu(x) = 0.5 x (1 + erf(x/sqrt(2))).
__device__ __forceinline__ float gelu_fast(float x) {
    const float t = fabsf(x) * 0.70710678118654752f;
    const float u = __fdividef(1.f, fmaf(0.3275911f, t, 1.f));
    float p = fmaf(1.061405429f, u, -1.453152027f);
    p = fmaf(p, u, 1.421413741f);
    p = fmaf(p, u, -0.284496736f);
    p = fmaf(p, u, 0.254829592f);
    p = p * u;
    const float e  = __expf(-t * t);
    const float er = copysignf(fmaf(-p, e, 1.f), x);
    return 0.5f * x * (1.f + er);
}

// ------- 1) depthwise 7x7 conv + bias: one block per (b,c) plane -------------
__global__ __launch_bounds__(256) void dwconv_kernel(
    const float* __restrict__ x, const float* __restrict__ cw,
    const float* __restrict__ cb)
{
    const int bc = blockIdx.x;            // b*DIM + c
    const int c  = bc & (DIM-1);

    __shared__ float sx[62][64];          // rows -3..58, cols -3..60 (pad 64)
    __shared__ float sw[49];

    const float* xp = x + (size_t)bc*HWc;
    const int t = threadIdx.x;
    if (t < 49) sw[t] = cw[c*49 + t];

    for (int i = t; i < 62*64; i += 256) {
        const int r = i >> 6, col = i & 63;
        const int gr = r - 3, gc = col - 3;
        float v = 0.f;
        if (gr >= 0 && gr < Hc && gc >= 0 && gc < Wc)
            v = xp[gr*Wc + gc];
        sx[r][col] = v;
    }
    __syncthreads();

    const float bias = cb[c];
    float* op = g_conv + (size_t)bc*HWc;
    const int col = t & 63, r0 = t >> 6;  // 4 rows x 64 cols per iteration
    if (col < Wc) {
        #pragma unroll
        for (int rr = r0; rr < Hc; rr += 4) {
            float acc = bias;
            #pragma unroll
            for (int ki = 0; ki < 7; ki++)
                #pragma unroll
                for (int kj = 0; kj < 7; kj++)
                    acc = fmaf(sx[rr+ki][col+kj], sw[ki*7+kj], acc);
            op[rr*Wc + col] = acc;
        }
    }
}

// ------- 2) LayerNorm over channels + NCHW->NHWC, emit fp16 ------------------
__global__ __launch_bounds__(256) void ln_kernel(
    const float* __restrict__ gamma, const float* __restrict__ beta)
{
    int tile = blockIdx.x;
    int b    = tile / (HWc/32);
    int pixbase = (tile % (HWc/32)) * 32;

    __shared__ float s[DIM][33];
    __shared__ float psum[8][32], psq[8][32];
    __shared__ float mu_s[32], rs_s[32];

    int t = threadIdx.x;
    int p = t & 31, gi = t >> 5;

    const float* base = g_conv + (size_t)b*DIM*HWc + pixbase;
    #pragma unroll
    for (int cc = 0; cc < 32; cc++) {
        int c = gi*32 + cc;
        s[c][p] = base[(size_t)c*HWc + p];
    }
    __syncthreads();

    float sum = 0.f, sq = 0.f;
    #pragma unroll
    for (int cc = 0; cc < 32; cc++) {
        float v = s[gi*32+cc][p];
        sum += v; sq = fmaf(v, v, sq);
    }
    psum[gi][p] = sum; psq[gi][p] = sq;
    __syncthreads();

    if (gi == 0) {
        float S = 0.f, Q = 0.f;
        #pragma unroll
        for (int k = 0; k < 8; k++) { S += psum[k][p]; Q += psq[k][p]; }
        float mu  = S * (1.f/DIM);
        float var = Q * (1.f/DIM) - mu*mu;
        mu_s[p] = mu;
        rs_s[p] = rsqrtf(var + 1e-6f);
    }
    __syncthreads();

    size_t tokbase = (size_t)b*HWc + pixbase;
    for (int i = t; i < 32*128; i += 256) {
        int pp = i >> 7, c2 = (i & 127) * 2;
        float mu = mu_s[pp], rs = rs_s[pp];
        float v0 = (s[c2  ][pp] - mu) * rs * gamma[c2  ] + beta[c2  ];
        float v1 = (s[c2+1][pp] - mu) * rs * gamma[c2+1] + beta[c2+1];
        *(uint32_t*)(g_a + (tokbase + pp)*DIM + c2) =
            pack2(__float2half_rn(v0), __float2half_rn(v1));
    }
}

// ------- 2b) transpose weights to fp16: w1[K,N]->w1t[N,K], w2 likewise -------
__global__ __launch_bounds__(256) void prep_w_kernel(
    const float* __restrict__ w1, const float* __restrict__ w2)
{
    int idx = blockIdx.x * 256 + threadIdx.x;
    if (idx < HID*DIM) {                       // w1t [n=1024][k=256]
        int n = idx >> 8, k = idx & 255;
        g_w1t[idx] = __float2half_rn(w1[(size_t)k*HID + n]);
    } else {                                   // w2t [n=256][k=1024]
        int j = idx - HID*DIM;
        int n = j >> 10, k = j & 1023;
        g_w2t[j] = __float2half_rn(w2[(size_t)k*DIM + n]);
    }
}

// ---------------- 3/4) HMMA fp16 GEMM (mma.sync.m16n8k16) --------------------
// CTA 128x128, BK=64, 256 threads, 2 CTAs/SM, 3-stage cp.async pipeline.
// Stage: A 16K | B 16K = 32KB; 3 stages = 96KB/CTA.
// LDSM addresses precomputed; per-k-step address = base ^ (32*ks).
// MODE 1: out = fp16(gelu_fast(acc+bias)) -> Oh [tok][HID]
// MODE 2: out = acc+bias -> fp32 NCHW (smem-transposed, coalesced)
#define STAGE  32768
#define GSMEM  (3*STAGE)     // 98304

template<int KTOT, int MODE>
__global__ __launch_bounds__(256, 2) void hgemm_kernel(
    const f16* __restrict__ A, const f16* __restrict__ Bw,
    const float* __restrict__ bias,
    f16* __restrict__ Oh, float* __restrict__ Of)
{
    extern __shared__ char smem[];
    __shared__ float sbias[128];

    const int tid  = threadIdx.x;
    const int wid  = tid >> 5, lane = tid & 31;
    const int warpM = wid >> 2, warpN = wid & 3;        // 2 x 4
    const int n0 = blockIdx.x * 128;
    const size_t m0 = (size_t)blockIdx.y * 128;

    if (tid < 128) sbias[tid] = bias[n0 + tid];

    const uint32_t sb = smem_u32(smem);

    // ---- producer: precomputed smem offsets + gmem row offsets --------------
    const f16* Abase = A + m0 * KTOT;
    const f16* Bbase = Bw + (size_t)n0 * KTOT;
    uint32_t soff[4], goff[4];
    #pragma unroll
    for (int it = 0; it < 4; it++) {
        const int chunk = tid + it * 256;               // 0..1023
        const uint32_t r = chunk >> 3, seg = chunk & 7;
        soff[it] = sw128(r*128 + seg*16);
        goff[it] = r * (uint32_t)KTOT + seg*8;
    }
    auto load_stage = [&](int c, int s) {
        const uint32_t st = sb + s * STAGE;
        const uint32_t k0 = (uint32_t)c * 64;
        #pragma unroll
        for (int it = 0; it < 4; it++) {
            CP16(st + soff[it],         Abase + goff[it] + k0);
            CP16(st + 16384 + soff[it], Bbase + goff[it] + k0);
        }
    };

    // ---- consumer: precomputed LDSM base offsets -----------------------------
    const int j  = lane >> 3, lr = lane & 7;
    const uint32_t mask = (uint32_t)lr << 4;
    uint32_t aoff[4], boff[2];
    #pragma unroll
    for (int mt = 0; mt < 4; mt++) {
        const uint32_t row = warpM*64 + ((j & 1) << 3) + lr + mt*16;
        aoff[mt] = row*128 + (((uint32_t)(j >> 1) << 4) ^ mask);
    }
    #pragma unroll
    for (int p = 0; p < 2; p++) {
        const uint32_t row = warpN*32 + ((j >> 1) << 3) + lr + p*16;
        boff[p] = 16384 + row*128 + (((uint32_t)(j & 1) << 4) ^ mask);
    }

    float acc[4][4][4] = {};

    const int NC = KTOT / 64;
    load_stage(0, 0); CP_COMMIT();
    if (NC > 1) { load_stage(1, 1); CP_COMMIT(); }

    int s_use = 0, s_load = 2;
    #pragma unroll 1
    for (int c = 0; c < NC; c++) {
        if (c + 1 < NC) { CP_WAIT(1); } else { CP_WAIT(0); }
        __syncthreads();
        if (c + 2 < NC) {
            load_stage(c + 2, s_load); CP_COMMIT();
            if (++s_load == 3) s_load = 0;
        }

        const uint32_t st = sb + s_use * STAGE;
        if (++s_use == 3) s_use = 0;
        const uint32_t a0 = st + aoff[0], a1 = st + aoff[1];
        const uint32_t a2 = st + aoff[2], a3 = st + aoff[3];
        const uint32_t b0 = st + boff[0], b1 = st + boff[1];

        #pragma unroll
        for (int ks = 0; ks < 4; ks++) {
            const uint32_t kx = 32u * ks;               // XOR bits [5:6]
            uint32_t bh[4][2];
            {
                uint32_t r[4];
                LDSM4(r, b0 ^ kx);
                bh[0][0]=r[0]; bh[0][1]=r[1]; bh[1][0]=r[2]; bh[1][1]=r[3];
                LDSM4(r, b1 ^ kx);
                bh[2][0]=r[0]; bh[2][1]=r[1]; bh[3][0]=r[2]; bh[3][1]=r[3];
            }
            uint32_t ah[4][4];
            LDSM4(ah[0], a0 ^ kx);
            LDSM4(ah[1], a1 ^ kx);
            LDSM4(ah[2], a2 ^ kx);
            LDSM4(ah[3], a3 ^ kx);

            #pragma unroll
            for (int mt = 0; mt < 4; mt++)
                #pragma unroll
                for (int nt = 0; nt < 4; nt++)
                    MMA16816(acc[mt][nt], ah[mt], bh[nt][0], bh[nt][1]);
        }
    }

    // ------------------------- epilogue -------------------------------------
    const int mlane = lane >> 2;         // row within 8-row group
    const int nlane = (lane & 3) * 2;    // even col pair

    if (MODE == 1) {
        #pragma unroll
        for (int mt = 0; mt < 4; mt++) {
            const size_t mA = m0 + warpM*64 + mt*16 + mlane;
            #pragma unroll
            for (int nt = 0; nt < 4; nt++) {
                const int nc = warpN*32 + nt*8 + nlane;
                const float b0 = sbias[nc], b1 = sbias[nc + 1];
                #pragma unroll
                for (int half = 0; half < 2; half++) {
                    float v0 = gelu_fast(acc[mt][nt][half*2]     + b0);
                    float v1 = gelu_fast(acc[mt][nt][half*2 + 1] + b1);
                    size_t o = (mA + half*8) * (size_t)HID + n0 + nc;
                    *(uint32_t*)(Oh + o) = pack2(__float2half_rn(v0),
                                                 __float2half_rn(v1));
                }
            }
        }
    } else {
        __syncthreads();                   // stage smem free for reuse
        float* sf = (float*)smem;          // [128 n][132 m] fp32 transpose tile
        #pragma unroll
        for (int mt = 0; mt < 4; mt++) {
            const int mA = warpM*64 + mt*16 + mlane;
            #pragma unroll
            for (int nt = 0; nt < 4; nt++) {
                const int nc = warpN*32 + nt*8 + nlane;
                sf[(nc    )*132 + mA    ] = acc[mt][nt][0];
                sf[(nc + 1)*132 + mA    ] = acc[mt][nt][1];
                sf[(nc    )*132 + mA + 8] = acc[mt][nt][2];
                sf[(nc + 1)*132 + mA + 8] = acc[mt][nt][3];
            }
        }
        __syncthreads();
        #pragma unroll 4
        for (int i = tid; i < 128*128; i += 256) {
            const int n = i >> 7, mm = i & 127;
            const int tok = (int)m0 + mm;
            const int b = tok / HWc, pix = tok % HWc;
            Of[((size_t)b*DIM + n0 + n)*HWc + pix] = sf[n*132 + mm] + sbias[n];
        }
    }
}

// ---------------- launch -----------------------------------------------------
extern "C" void kernel_launch(void* const* d_in, const int* in_sizes, int n_in,
                              void* d_out, int out_size)
{
    const float* x      = (const float*)d_in[0];
    const float* conv_w = (const float*)d_in[1];
    const float* conv_b = (const float*)d_in[2];
    const float* ln_g   = (const float*)d_in[3];
    const float* ln_b   = (const float*)d_in[4];
    const float* w1     = (const float*)d_in[5];
    const float* b1     = (const float*)d_in[6];
    const float* w2     = (const float*)d_in[7];
    const float* b2     = (const float*)d_in[8];
    float* out = (float*)d_out;

    f16 *p_a, *p_h, *p_w1t, *p_w2t;
    cudaGetSymbolAddress((void**)&p_a,   g_a);
    cudaGetSymbolAddress((void**)&p_h,   g_h);
    cudaGetSymbolAddress((void**)&p_w1t, g_w1t);
    cudaGetSymbolAddress((void**)&p_w2t, g_w2t);

    cudaFuncSetAttribute((const void*)hgemm_kernel<DIM, 1>,
                         cudaFuncAttributeMaxDynamicSharedMemorySize, GSMEM);
    cudaFuncSetAttribute((const void*)hgemm_kernel<HID, 2>,
                         cudaFuncAttributeMaxDynamicSharedMemorySize, GSMEM);

    dwconv_kernel<<<Bc*DIM, 256>>>(x, conv_w, conv_b);
    ln_kernel<<<TOK/32, 256>>>(ln_g, ln_b);
    prep_w_kernel<<<(2*HID*DIM)/256, 256>>>(w1, w2);

    // GEMM1: [TOK,256] x w1t -> GELU -> h (fp16)
    hgemm_kernel<DIM, 1><<<dim3(HID/128, TOK/128), 256, GSMEM>>>(
        p_a, p_w1t, b1, p_h, nullptr);
    // GEMM2: [TOK,1024] x w2t -> +b2 -> fp32 NCHW out
    hgemm_kernel<HID, 2><<<dim3(DIM/128, TOK/128), 256, GSMEM>>>(
        p_h, p_w2t, b2, nullptr, out);
}